// round 13
// baseline (speedup 1.0000x reference)
#include <cuda_runtime.h>
#include <math.h>
#include <stdint.h>

// Problem constants
#define Bq 512
#define Tt 10
#define Nn 50
#define Hh 200
#define Ee 10000
#define Rr 200
#define H3 600
#define H2 400
#define BE (Bq*Ee)

// ---------------- scratch (static __device__, no allocations) ----------------
__device__ float g_proj_s[Ee*Hh];
__device__ float g_proj_o[Ee*Hh];
__device__ float g_x_s[Bq*H2];
__device__ float g_x_o[Bq*H2];
__device__ float g_bias_s[Bq*Hh];
__device__ float g_bias_o[Bq*Hh];
__device__ float g_seq_s[Bq*Tt*H3];
__device__ float g_seq_o[Bq*Tt*H3];
__device__ float g_gi_s[Bq*Tt*H3];
__device__ float g_gi_o[Bq*Tt*H3];
__device__ float g_h_s[Bq*Hh];
__device__ float g_h_o[Bq*Hh];
__device__ float g_feat_s[Bq*H3];
__device__ float g_feat_o[Bq*H3];
__device__ float g_lp0[Bq];
__device__ float g_lp1[Bq];
__device__ int   g_sidx[Bq];
__device__ int   g_oidx[Bq];

// tf32-rounded copies of GEMM inputs (rounded ONCE; GEMM feeds raw bits to MMA)
__device__ float g_ent_r [Ee*Hh];
__device__ float g_wa_s  [Hh*H3];
__device__ float g_wa_o  [Hh*H3];
__device__ float g_wih_s [H3*H3];
__device__ float g_wih_o [H3*H3];
__device__ float g_wlin_s[Ee*H3];
__device__ float g_wlin_o[Ee*H3];

__device__ __forceinline__ float tanh_fast(float x) {
    float y;
    asm("tanh.approx.f32 %0, %1;" : "=f"(y) : "f"(x));
    return y;
}

__device__ __forceinline__ uint32_t cvt_tf32(float x) {
    uint32_t y;
    asm("cvt.rna.tf32.f32 %0, %1;" : "=r"(y) : "f"(x));
    return y;
}
__device__ __forceinline__ float round_tf32(float x) {
    return __uint_as_float(cvt_tf32(x));
}

__device__ __forceinline__ void mma_tf32(float* d, const uint32_t* a, const uint32_t* b) {
    asm volatile(
        "mma.sync.aligned.m16n8k8.row.col.f32.tf32.tf32.f32 "
        "{%0,%1,%2,%3}, {%4,%5,%6,%7}, {%8,%9}, {%0,%1,%2,%3};"
        : "+f"(d[0]), "+f"(d[1]), "+f"(d[2]), "+f"(d[3])
        : "r"(a[0]), "r"(a[1]), "r"(a[2]), "r"(a[3]), "r"(b[0]), "r"(b[1]));
}

__device__ __forceinline__ void cp16(uint32_t dst, const float* src) {
    asm volatile("cp.async.cg.shared.global [%0], [%1], 16;" :: "r"(dst), "l"(src));
}
__device__ __forceinline__ void cp_commit() {
    asm volatile("cp.async.commit_group;");
}

// ---------------- pre-round all static GEMM inputs to tf32 -------------------
__global__ void round_all(const float* __restrict__ ent,
                          const float* __restrict__ wa_s, const float* __restrict__ wa_o,
                          const float* __restrict__ wih_s, const float* __restrict__ wih_o,
                          const float* __restrict__ wlin_s, const float* __restrict__ wlin_o)
{
    const float* src; float* dst; int n4;
    switch (blockIdx.y) {
        case 0: src = ent;    dst = g_ent_r;  n4 = Ee*Hh/4;  break;
        case 1: src = wa_s;   dst = g_wa_s;   n4 = Hh*H3/4;  break;
        case 2: src = wa_o;   dst = g_wa_o;   n4 = Hh*H3/4;  break;
        case 3: src = wih_s;  dst = g_wih_s;  n4 = H3*H3/4;  break;
        case 4: src = wih_o;  dst = g_wih_o;  n4 = H3*H3/4;  break;
        case 5: src = wlin_s; dst = g_wlin_s; n4 = Ee*H3/4;  break;
        default: src = wlin_o; dst = g_wlin_o; n4 = Ee*H3/4; break;
    }
    int stride = gridDim.x * blockDim.x;
    for (int i = blockIdx.x * blockDim.x + threadIdx.x; i < n4; i += stride) {
        float4 v = ((const float4*)src)[i];
        v.x = round_tf32(v.x); v.y = round_tf32(v.y);
        v.z = round_tf32(v.z); v.w = round_tf32(v.w);
        ((float4*)dst)[i] = v;
    }
}

// ---------------- parallel stable descending argsort (rank-based) ------------
__global__ void sort_kernel(const int* __restrict__ s_hlen, const int* __restrict__ o_hlen)
{
    __shared__ int sv[Bq], ov[Bq];
    int t = threadIdx.x;
    int b = t & 511;
    if (t < 512) sv[b] = s_hlen[b]; else ov[b] = o_hlen[b];
    __syncthreads();
    const int* L = (t < 512) ? sv : ov;
    int lv = L[b];
    int r = 0;
    for (int j = 0; j < Bq; j++) {
        int v = L[j];
        r += (v > lv) || (v == lv && j < b);
    }
    if (t < 512) g_sidx[r] = b; else g_oidx[r] = b;
}

// ---------------- gather X = [ent[sid] || ent[rid]] (tf32-rounded) -----------
__global__ void gather_x(const int* __restrict__ trip, const float* __restrict__ ent)
{
    int b = blockIdx.x, z = blockIdx.y;
    float* X = (z ? g_x_o : g_x_s) + (size_t)b * H2;
    int scol = z ? 2 : 0;
    int sid = trip[b * 3 + scol], rid = trip[b * 3 + 1];
    for (int i = threadIdx.x; i < Hh; i += 128) {
        X[i]      = round_tf32(ent[(size_t)sid * Hh + i]);
        X[Hh + i] = round_tf32(ent[(size_t)rid * Hh + i]);
    }
}

// ============ tf32 tensor-core GEMM: C[M,N] = A[M,K] @ W[N,K]^T (+bias) ======
// 128 threads = 4 warps; CTA tile 128x64; warp tile 64x32 = 4x4 m16n8k8
// (1.5 LDS per HMMA, 16-deep HMMA chain per warp per k-tile).
// Pair-pipelined 6-stage smem ring; one wait+sync per PAIR of 8-deep k-tiles.
// Inputs must be tf32-pre-rounded. Scalar C stores (C may be misaligned).
__device__ __forceinline__
void gemm_tc_body(const float* __restrict__ A, int lda,
                  const float* __restrict__ W, int ldw,
                  const float* __restrict__ bias,
                  float* __restrict__ C, int ldc,
                  int M, int N, int K)
{
    __shared__ float As[6][128][8];
    __shared__ float Ws[6][64][8];

    const int tid  = threadIdx.x;
    const int bm   = blockIdx.y * 128;
    const int bn   = blockIdx.x * 64;
    const int wid  = tid >> 5, lane = tid & 31;
    const int gid  = lane >> 2, tig = lane & 3;
    const int wm   = (wid & 1) * 64;     // warp M offset (2 m-positions)
    const int wn   = (wid >> 1) * 32;    // warp N offset (2 n-positions)

    // ---- staging setup ----
    // A: each thread stages row tid (both 16B chunks)
    int rA = bm + tid; if (rA > M - 1) rA = M - 1;
    const float* aSrc = A + (size_t)rA * lda;
    uint32_t aDst0 = (uint32_t)__cvta_generic_to_shared(
        &As[0][tid][4 * (0 ^ ((tid >> 2) & 1))]);
    uint32_t aDst1 = (uint32_t)__cvta_generic_to_shared(
        &As[0][tid][4 * (1 ^ ((tid >> 2) & 1))]);
    // W: row = tid>>1, chunk = tid&1
    const int sn = tid >> 1;
    const int sc = tid & 1;
    int rW = bn + sn; if (rW > N - 1) rW = N - 1;
    const float* wSrc = W + (size_t)rW * ldw + 4 * sc;
    uint32_t wDst = (uint32_t)__cvta_generic_to_shared(
        &Ws[0][sn][4 * (sc ^ ((sn >> 2) & 1))]);

    const uint32_t A_ST = 128 * 8 * 4;
    const uint32_t W_ST = 64 * 8 * 4;

    const int nt = K >> 3;
    const int np = (nt + 1) >> 1;

    // prologue: pair 0 -> stages {0,1}; pair 1 -> stages {2,3}
    {
        cp16(aDst0, aSrc);     cp16(aDst1, aSrc + 4);
        cp16(wDst, wSrc);
        if (1 < nt) {
            cp16(aDst0 + A_ST, aSrc + 8);  cp16(aDst1 + A_ST, aSrc + 12);
            cp16(wDst + W_ST, wSrc + 8);
        }
        cp_commit();
        if (2 < nt) {
            cp16(aDst0 + 2 * A_ST, aSrc + 16);  cp16(aDst1 + 2 * A_ST, aSrc + 20);
            cp16(wDst + 2 * W_ST, wSrc + 16);
            if (3 < nt) {
                cp16(aDst0 + 3 * A_ST, aSrc + 24);  cp16(aDst1 + 3 * A_ST, aSrc + 28);
                cp16(wDst + 3 * W_ST, wSrc + 24);
            }
        }
        cp_commit();
    }

    float acc[4][4][4];
#pragma unroll
    for (int i = 0; i < 4; i++)
#pragma unroll
        for (int j = 0; j < 4; j++)
#pragma unroll
            for (int e = 0; e < 4; e++) acc[i][j][e] = 0.f;

    const int s   = gid >> 2;
    const int klo = 4 * s + tig;
    const int khi = 4 - 4 * s + tig;

    for (int p = 0; p < np; p++) {
        if (p < np - 1) asm volatile("cp.async.wait_group 1;");
        else            asm volatile("cp.async.wait_group 0;");
        __syncthreads();

        // prefetch pair p+2 into pair-slot (p+2)%3 (consumed at iter p-1, safe)
        {
            int q = p + 2;
            if (q < np) {
                int st = (q - (q / 3) * 3) * 2;     // (q%3)*2
                int kt0 = q * 2;
                cp16(aDst0 + (uint32_t)st * A_ST, aSrc + kt0 * 8);
                cp16(aDst1 + (uint32_t)st * A_ST, aSrc + kt0 * 8 + 4);
                cp16(wDst + (uint32_t)st * W_ST, wSrc + kt0 * 8);
                if (kt0 + 1 < nt) {
                    cp16(aDst0 + (uint32_t)(st + 1) * A_ST, aSrc + (kt0 + 1) * 8);
                    cp16(aDst1 + (uint32_t)(st + 1) * A_ST, aSrc + (kt0 + 1) * 8 + 4);
                    cp16(wDst + (uint32_t)(st + 1) * W_ST, wSrc + (kt0 + 1) * 8);
                }
            }
            cp_commit();
        }

        // consume the two sub-tiles of pair p
        const int base = (p - (p / 3) * 3) * 2;     // (p%3)*2
#pragma unroll
        for (int sub = 0; sub < 2; sub++) {
            int kt = 2 * p + sub;
            if (kt >= nt) break;
            const int buf = base + sub;
            uint32_t afr[4][4], bfr[4][2];
#pragma unroll
            for (int i = 0; i < 4; i++) {
                int mb = wm + 16 * i + gid;
                afr[i][0] = __float_as_uint(As[buf][mb    ][klo]);
                afr[i][1] = __float_as_uint(As[buf][mb + 8][klo]);
                afr[i][2] = __float_as_uint(As[buf][mb    ][khi]);
                afr[i][3] = __float_as_uint(As[buf][mb + 8][khi]);
            }
#pragma unroll
            for (int j = 0; j < 4; j++) {
                int nb = wn + 8 * j + gid;
                bfr[j][0] = __float_as_uint(Ws[buf][nb][klo]);
                bfr[j][1] = __float_as_uint(Ws[buf][nb][khi]);
            }
#pragma unroll
            for (int i = 0; i < 4; i++)
#pragma unroll
                for (int j = 0; j < 4; j++)
                    mma_tf32(acc[i][j], afr[i], bfr[j]);
        }
    }

    // epilogue (scalar stores — C may be misaligned, e.g. d_out+1)
#pragma unroll
    for (int i = 0; i < 4; i++) {
        int r0 = bm + wm + 16 * i + gid;
        int r1 = r0 + 8;
#pragma unroll
        for (int j = 0; j < 4; j++) {
            int c = bn + wn + 8 * j + 2 * tig;
            if (c < N) {
                float b0 = bias ? bias[c]     : 0.f;
                float b1 = bias ? bias[c + 1] : 0.f;
                if (r0 < M) {
                    C[(size_t)r0 * ldc + c]     = acc[i][j][0] + b0;
                    C[(size_t)r0 * ldc + c + 1] = acc[i][j][1] + b1;
                }
                if (r1 < M) {
                    C[(size_t)r1 * ldc + c]     = acc[i][j][2] + b0;
                    C[(size_t)r1 * ldc + c + 1] = acc[i][j][3] + b1;
                }
            }
        }
    }
}

struct GemmArgs {
    const float* A; int lda;
    const float* W; int ldw;
    const float* bias;
    float* C; int ldc;
};

__global__ __launch_bounds__(128)
void gemm_tc_dual(GemmArgs a0, GemmArgs a1, int M, int N, int K)
{
    const GemmArgs& g = blockIdx.z ? a1 : a0;
    gemm_tc_body(g.A, g.lda, g.W, g.ldw, g.bias, g.C, g.ldc, M, N, K);
}

// ---------------- attention (both streams via blockIdx.y) --------------------
struct AttnArgs {
    const int* neigh; const int* nlen; const int* hlen;
    const float* proj; const float* bias; const float* v;
    float* seq; int scol;
};

__global__ void attn_dual(AttnArgs a0, AttnArgs a1,
                          const int* __restrict__ trip,
                          const float* __restrict__ ent,
                          const float* __restrict__ rel)
{
    const AttnArgs& a = blockIdx.y ? a1 : a0;
    const int bt = blockIdx.x;
    const int b = bt / Tt, t = bt % Tt;
    __shared__ float s_bias[Hh], s_v[Hh];
    __shared__ float s_logit[Nn], s_w[Nn];
    __shared__ int s_nidx[Nn];
    const int tid = threadIdx.x;
    for (int g = tid; g < Hh; g += 256) { s_bias[g] = a.bias[b * Hh + g]; s_v[g] = a.v[g]; }
    for (int n = tid; n < Nn; n += 256) s_nidx[n] = a.neigh[((size_t)b * Tt + t) * Nn + n];
    __syncthreads();
    const int nl = a.nlen[b * Tt + t];
    const int warp = tid >> 5, lane = tid & 31;
    for (int n = warp; n < nl; n += 8) {
        const float* pr = a.proj + (size_t)s_nidx[n] * Hh;
        float acc = 0.f;
        for (int g = lane; g < Hh; g += 32)
            acc += tanh_fast(pr[g] + s_bias[g]) * s_v[g];
        for (int o = 16; o; o >>= 1) acc += __shfl_xor_sync(0xffffffffu, acc, o);
        if (lane == 0) s_logit[n] = acc;
    }
    __syncthreads();
    if (warp == 0) {
        float m = -3.4e38f;
        for (int n = lane; n < nl; n += 32) m = fmaxf(m, s_logit[n]);
        for (int o = 16; o; o >>= 1) m = fmaxf(m, __shfl_xor_sync(0xffffffffu, m, o));
        float s = 0.f;
        for (int n = lane; n < nl; n += 32) { float e = expf(s_logit[n] - m); s_w[n] = e; s += e; }
        for (int o = 16; o; o >>= 1) s += __shfl_xor_sync(0xffffffffu, s, o);
        float inv = 1.f / s;
        for (int n = lane; n < nl; n += 32) s_w[n] *= inv;
    }
    __syncthreads();
    const float msk = (t < a.hlen[b]) ? 1.f : 0.f;
    const int sid = trip[b * 3 + a.scol], rid = trip[b * 3 + 1];
    float* out = a.seq + ((size_t)b * Tt + t) * H3;
    for (int h = tid; h < Hh; h += 256) {
        float acc = 0.f;
        for (int n = 0; n < nl; n++) acc += s_w[n] * ent[(size_t)s_nidx[n] * Hh + h];
        out[h]          = round_tf32(acc * msk);
        out[Hh + h]     = round_tf32(ent[(size_t)sid * Hh + h] * msk);
        out[2 * Hh + h] = round_tf32(rel[(size_t)rid * Hh + h] * msk);
    }
}

// ---------------- fused GRU: whole T-loop in one launch -----------------------
__global__ __launch_bounds__(256)
void gru_fused(const float* __restrict__ Whh_s, const float* __restrict__ bhh_s,
               const float* __restrict__ Whh_o, const float* __restrict__ bhh_o,
               const int* __restrict__ slen, const int* __restrict__ olen)
{
    const int z = blockIdx.y;
    const float* Whh = z ? Whh_o : Whh_s;
    const float* bhh = z ? bhh_o : bhh_s;
    const float* gi  = z ? g_gi_o : g_gi_s;
    float* hout      = z ? g_h_o : g_h_s;
    const int* len   = z ? olen : slen;
    const int b0 = blockIdx.x * 8;
    const int tid = threadIdx.x;

    __shared__ float h_sm[8][Hh];
    __shared__ float gh_sm[8][H3];
    __shared__ int   len_sm[8];

    for (int i = tid; i < 8 * Hh; i += 256) h_sm[i / Hh][i % Hh] = 0.f;
    if (tid < 8) len_sm[tid] = len[b0 + tid];
    __syncthreads();

    for (int t = 0; t < Tt; t++) {
        for (int j = tid; j < H3; j += 256) {
            const float* wrow = Whh + (size_t)j * Hh;
            float acc[8];
#pragma unroll
            for (int b = 0; b < 8; b++) acc[b] = 0.f;
            for (int k = 0; k < Hh; k += 4) {
                float4 w = *(const float4*)(wrow + k);
#pragma unroll
                for (int b = 0; b < 8; b++) {
                    float4 h4 = *(const float4*)&h_sm[b][k];
                    acc[b] += w.x * h4.x + w.y * h4.y + w.z * h4.z + w.w * h4.w;
                }
            }
            float bb = bhh[j];
#pragma unroll
            for (int b = 0; b < 8; b++) gh_sm[b][j] = acc[b] + bb;
        }
        __syncthreads();

        for (int idx = tid; idx < 8 * Hh; idx += 256) {
            int b = idx / Hh, jj = idx % Hh;
            if (t < len_sm[b]) {
                const float* gib = gi + ((size_t)(b0 + b) * Tt + t) * H3;
                float ir = gib[jj], iz = gib[Hh + jj], in = gib[2 * Hh + jj];
                float hr = gh_sm[b][jj], hz = gh_sm[b][Hh + jj], hn = gh_sm[b][2 * Hh + jj];
                float rg = 1.f / (1.f + expf(-(ir + hr)));
                float zg = 1.f / (1.f + expf(-(iz + hz)));
                float ng = tanhf(in + rg * hn);
                h_sm[b][jj] = (1.f - zg) * ng + zg * h_sm[b][jj];
            }
        }
        __syncthreads();
    }

    for (int i = tid; i < 8 * Hh; i += 256)
        hout[(size_t)(b0 + i / Hh) * Hh + (i % Hh)] = h_sm[i / Hh][i % Hh];
}

// ---------------- final feature assembly (tf32-rounded; GEMM input) ----------
__global__ void feat_kernel(const int* __restrict__ trip, const int* __restrict__ idx,
                            int scol, const float* __restrict__ ent,
                            const float* __restrict__ rel, const float* __restrict__ h,
                            float* __restrict__ feat)
{
    int b = blockIdx.x;
    int p = idx[b];
    int sid = trip[p * 3 + scol], rid = trip[p * 3 + 1];
    for (int i = threadIdx.x; i < Hh; i += 256) {
        feat[(size_t)b * H3 + i]        = round_tf32(ent[(size_t)sid * Hh + i]);
        feat[(size_t)b * H3 + Hh + i]   = round_tf32(h[(size_t)p * Hh + i]);
        feat[(size_t)b * H3 + 2*Hh + i] = round_tf32(rel[(size_t)rid * Hh + i]);
    }
}

// ---------------- cross-entropy per-row log-prob of label --------------------
__global__ void ce_kernel(const float* __restrict__ pred, const int* __restrict__ trip,
                          const int* __restrict__ idx, int labcol, float* __restrict__ lp)
{
    int b = blockIdx.x;
    const float* row = pred + (size_t)b * Ee;
    int tid = threadIdx.x;
    int lane = tid & 31, warp = tid >> 5;
    __shared__ float sred[8];

    float m = -3.4e38f;
    for (int i = tid; i < Ee; i += 256) m = fmaxf(m, row[i]);
    for (int o = 16; o; o >>= 1) m = fmaxf(m, __shfl_xor_sync(0xffffffffu, m, o));
    if (lane == 0) sred[warp] = m;
    __syncthreads();
    if (tid == 0) {
        float mm = sred[0];
        for (int i = 1; i < 8; i++) mm = fmaxf(mm, sred[i]);
        sred[0] = mm;
    }
    __syncthreads();
    m = sred[0];
    __syncthreads();

    float s = 0.f;
    for (int i = tid; i < Ee; i += 256) s += expf(row[i] - m);
    for (int o = 16; o; o >>= 1) s += __shfl_xor_sync(0xffffffffu, s, o);
    if (lane == 0) sred[warp] = s;
    __syncthreads();
    if (tid == 0) {
        float st = 0.f;
        for (int i = 0; i < 8; i++) st += sred[i];
        int lab = trip[idx[b] * 3 + labcol];
        lp[b] = row[lab] - m - logf(st);
    }
}

// ---------------- finalize: loss + index outputs ------------------------------
__global__ void finalize_kernel(float* __restrict__ out)
{
    int tid = threadIdx.x;
    if (tid == 0) {
        double a = 0.0, c = 0.0;
        for (int b = 0; b < Bq; b++) { a += (double)g_lp0[b]; c += (double)g_lp1[b]; }
        out[0] = (float)(-(a / (double)Bq) - (c / (double)Bq));
    }
    for (int b = tid; b < Bq; b += blockDim.x) {
        out[1 + 2 * (size_t)BE + b]       = (float)g_oidx[b];
        out[1 + 2 * (size_t)BE + Bq + b]  = (float)g_sidx[b];
    }
}

// ---------------- host-side orchestration ------------------------------------
extern "C" void kernel_launch(void* const* d_in, const int* in_sizes, int n_in,
                              void* d_out, int out_size)
{
    const int*   trip     = (const int*)d_in[0];
    const int*   s_neigh  = (const int*)d_in[1];
    const int*   s_nlen   = (const int*)d_in[2];
    const int*   s_hlen   = (const int*)d_in[3];
    const int*   o_neigh  = (const int*)d_in[4];
    const int*   o_nlen   = (const int*)d_in[5];
    const int*   o_hlen   = (const int*)d_in[6];
    const float* ent      = (const float*)d_in[7];
    const float* rel      = (const float*)d_in[8];
    const float* attn_s_w = (const float*)d_in[9];
    const float* attn_s_b = (const float*)d_in[10];
    const float* v_s      = (const float*)d_in[11];
    const float* attn_o_w = (const float*)d_in[12];
    const float* attn_o_b = (const float*)d_in[13];
    const float* v_o      = (const float*)d_in[14];
    const float* sub_w_ih = (const float*)d_in[15];
    const float* sub_w_hh = (const float*)d_in[16];
    const float* sub_b_ih = (const float*)d_in[17];
    const float* sub_b_hh = (const float*)d_in[18];
    const float* ob_w_ih  = (const float*)d_in[19];
    const float* ob_w_hh  = (const float*)d_in[20];
    const float* ob_b_ih  = (const float*)d_in[21];
    const float* ob_b_hh  = (const float*)d_in[22];
    const float* lin_sub_w = (const float*)d_in[23];
    const float* lin_sub_b = (const float*)d_in[24];
    const float* lin_ob_w  = (const float*)d_in[25];
    const float* lin_ob_b  = (const float*)d_in[26];
    float* out = (float*)d_out;

    float *proj_s, *proj_o, *x_s, *x_o, *bias_s, *bias_o, *seq_s, *seq_o;
    float *gi_s, *gi_o, *h_s, *h_o, *feat_s, *feat_o, *lp0, *lp1;
    float *ent_r, *wa_s, *wa_o, *wih_s, *wih_o, *wlin_s, *wlin_o;
    int *sidx, *oidx;
    cudaGetSymbolAddress((void**)&proj_s, g_proj_s);
    cudaGetSymbolAddress((void**)&proj_o, g_proj_o);
    cudaGetSymbolAddress((void**)&x_s,    g_x_s);
    cudaGetSymbolAddress((void**)&x_o,    g_x_o);
    cudaGetSymbolAddress((void**)&bias_s, g_bias_s);
    cudaGetSymbolAddress((void**)&bias_o, g_bias_o);
    cudaGetSymbolAddress((void**)&seq_s,  g_seq_s);
    cudaGetSymbolAddress((void**)&seq_o,  g_seq_o);
    cudaGetSymbolAddress((void**)&gi_s,   g_gi_s);
    cudaGetSymbolAddress((void**)&gi_o,   g_gi_o);
    cudaGetSymbolAddress((void**)&h_s,    g_h_s);
    cudaGetSymbolAddress((void**)&h_o,    g_h_o);
    cudaGetSymbolAddress((void**)&feat_s, g_feat_s);
    cudaGetSymbolAddress((void**)&feat_o, g_feat_o);
    cudaGetSymbolAddress((void**)&lp0,    g_lp0);
    cudaGetSymbolAddress((void**)&lp1,    g_lp1);
    cudaGetSymbolAddress((void**)&sidx,   g_sidx);
    cudaGetSymbolAddress((void**)&oidx,   g_oidx);
    cudaGetSymbolAddress((void**)&ent_r,  g_ent_r);
    cudaGetSymbolAddress((void**)&wa_s,   g_wa_s);
    cudaGetSymbolAddress((void**)&wa_o,   g_wa_o);
    cudaGetSymbolAddress((void**)&wih_s,  g_wih_s);
    cudaGetSymbolAddress((void**)&wih_o,  g_wih_o);
    cudaGetSymbolAddress((void**)&wlin_s, g_wlin_s);
    cudaGetSymbolAddress((void**)&wlin_o, g_wlin_o);

    // 0) pre-round all static GEMM inputs to tf32
    round_all<<<dim3(256, 7), 256>>>(ent, attn_s_w, attn_o_w,
                                     sub_w_ih, ob_w_ih, lin_sub_w, lin_ob_w);

    // 1) sort + X gather (rounded)
    sort_kernel<<<1, 1024>>>(s_hlen, o_hlen);
    gather_x<<<dim3(Bq, 2), 128>>>(trip, ent);

    // 2) entity projections (dual)  M=Ee,N=Hh,K=Hh
    {
        GemmArgs a0{ent_r, Hh, wa_s, H3, nullptr, proj_s, Hh};
        GemmArgs a1{ent_r, Hh, wa_o, H3, nullptr, proj_o, Hh};
        dim3 g((Hh + 63) / 64, (Ee + 127) / 128, 2);
        gemm_tc_dual<<<g, 128>>>(a0, a1, Ee, Hh, Hh);
    }

    // 3) bias GEMM (dual)  M=Bq,N=Hh,K=2H
    {
        GemmArgs a0{x_s, H2, wa_s + Hh, H3, attn_s_b, bias_s, Hh};
        GemmArgs a1{x_o, H2, wa_o + Hh, H3, attn_o_b, bias_o, Hh};
        dim3 g((Hh + 63) / 64, (Bq + 127) / 128, 2);
        gemm_tc_dual<<<g, 128>>>(a0, a1, Bq, Hh, H2);
    }

    // 4) attention (both streams, one launch)
    {
        AttnArgs a0{s_neigh, s_nlen, s_hlen, proj_s, bias_s, v_s, seq_s, 0};
        AttnArgs a1{o_neigh, o_nlen, o_hlen, proj_o, bias_o, v_o, seq_o, 2};
        attn_dual<<<dim3(Bq * Tt, 2), 256>>>(a0, a1, trip, ent, rel);
    }

    // 5) GRU input gates (dual)  M=B*T,N=3H,K=3H
    {
        GemmArgs a0{seq_s, H3, wih_s, H3, sub_b_ih, gi_s, H3};
        GemmArgs a1{seq_o, H3, wih_o, H3, ob_b_ih,  gi_o, H3};
        dim3 g((H3 + 63) / 64, (Bq * Tt + 127) / 128, 2);
        gemm_tc_dual<<<g, 128>>>(a0, a1, Bq * Tt, H3, H3);
    }

    // 6) fused GRU — whole T-loop, both streams, one launch
    gru_fused<<<dim3(Bq / 8, 2), 256>>>(sub_w_hh, sub_b_hh, ob_w_hh, ob_b_hh,
                                        s_hlen, o_hlen);

    // 7) permuted feature assembly
    feat_kernel<<<Bq, 256>>>(trip, sidx, 0, ent, rel, h_s, feat_s);
    feat_kernel<<<Bq, 256>>>(trip, oidx, 2, ent, rel, h_o, feat_o);

    // 8) prediction GEMMs into d_out (dual)  M=Bq,N=Ee,K=3H
    //    layout: [loss(1) | sub_pred(B*E) | ob_pred(B*E) | o_idx(B) | s_idx(B)]
    {
        GemmArgs a0{feat_s, H3, wlin_s, H3, lin_sub_b, out + 1 + (size_t)BE, Ee};
        GemmArgs a1{feat_o, H3, wlin_o, H3, lin_ob_b,  out + 1,              Ee};
        dim3 g((Ee + 63) / 64, (Bq + 127) / 128, 2);
        gemm_tc_dual<<<g, 128>>>(a0, a1, Bq, Ee, H3);
    }

    // 9) CE log-probs + finalize
    ce_kernel<<<Bq, 256>>>(out + 1 + (size_t)BE, trip, sidx, 2, lp0);
    ce_kernel<<<Bq, 256>>>(out + 1,              trip, oidx, 0, lp1);
    finalize_kernel<<<1, 512>>>(out);
}

// round 14
// speedup vs baseline: 1.0838x; 1.0838x over previous
#include <cuda_runtime.h>
#include <math.h>
#include <stdint.h>

// Problem constants
#define Bq 512
#define Tt 10
#define Nn 50
#define Hh 200
#define Ee 10000
#define Rr 200
#define H3 600
#define H2 400
#define BE (Bq*Ee)

// ---------------- scratch (static __device__, no allocations) ----------------
__device__ float g_proj_s[Ee*Hh];
__device__ float g_proj_o[Ee*Hh];
__device__ float g_x_s[Bq*H2];
__device__ float g_x_o[Bq*H2];
__device__ float g_bias_s[Bq*Hh];
__device__ float g_bias_o[Bq*Hh];
__device__ float g_seq_s[Bq*Tt*H3];
__device__ float g_seq_o[Bq*Tt*H3];
__device__ float g_gi_s[Bq*Tt*H3];
__device__ float g_gi_o[Bq*Tt*H3];
__device__ float g_h_s[Bq*Hh];
__device__ float g_h_o[Bq*Hh];
__device__ float g_feat_s[Bq*H3];
__device__ float g_feat_o[Bq*H3];
__device__ float g_lp0[Bq];
__device__ float g_lp1[Bq];
__device__ int   g_sidx[Bq];
__device__ int   g_oidx[Bq];

// tf32-rounded copies of GEMM inputs (rounded ONCE; GEMM feeds raw bits to MMA)
__device__ float g_ent_r [Ee*Hh];
__device__ float g_wa_s  [Hh*H3];
__device__ float g_wa_o  [Hh*H3];
__device__ float g_wih_s [H3*H3];
__device__ float g_wih_o [H3*H3];
__device__ float g_wlin_s[Ee*H3];
__device__ float g_wlin_o[Ee*H3];

__device__ __forceinline__ float tanh_fast(float x) {
    float y;
    asm("tanh.approx.f32 %0, %1;" : "=f"(y) : "f"(x));
    return y;
}

__device__ __forceinline__ uint32_t cvt_tf32(float x) {
    uint32_t y;
    asm("cvt.rna.tf32.f32 %0, %1;" : "=r"(y) : "f"(x));
    return y;
}
__device__ __forceinline__ float round_tf32(float x) {
    return __uint_as_float(cvt_tf32(x));
}

__device__ __forceinline__ void mma_tf32(float* d, const uint32_t* a, const uint32_t* b) {
    asm volatile(
        "mma.sync.aligned.m16n8k8.row.col.f32.tf32.tf32.f32 "
        "{%0,%1,%2,%3}, {%4,%5,%6,%7}, {%8,%9}, {%0,%1,%2,%3};"
        : "+f"(d[0]), "+f"(d[1]), "+f"(d[2]), "+f"(d[3])
        : "r"(a[0]), "r"(a[1]), "r"(a[2]), "r"(a[3]), "r"(b[0]), "r"(b[1]));
}

__device__ __forceinline__ void cp16(uint32_t dst, const float* src) {
    asm volatile("cp.async.cg.shared.global [%0], [%1], 16;" :: "r"(dst), "l"(src));
}
__device__ __forceinline__ void cp_commit() {
    asm volatile("cp.async.commit_group;");
}

// ---------------- pre-round all static GEMM inputs to tf32 -------------------
__global__ void round_all(const float* __restrict__ ent,
                          const float* __restrict__ wa_s, const float* __restrict__ wa_o,
                          const float* __restrict__ wih_s, const float* __restrict__ wih_o,
                          const float* __restrict__ wlin_s, const float* __restrict__ wlin_o)
{
    const float* src; float* dst; int n4;
    switch (blockIdx.y) {
        case 0: src = ent;    dst = g_ent_r;  n4 = Ee*Hh/4;  break;
        case 1: src = wa_s;   dst = g_wa_s;   n4 = Hh*H3/4;  break;
        case 2: src = wa_o;   dst = g_wa_o;   n4 = Hh*H3/4;  break;
        case 3: src = wih_s;  dst = g_wih_s;  n4 = H3*H3/4;  break;
        case 4: src = wih_o;  dst = g_wih_o;  n4 = H3*H3/4;  break;
        case 5: src = wlin_s; dst = g_wlin_s; n4 = Ee*H3/4;  break;
        default: src = wlin_o; dst = g_wlin_o; n4 = Ee*H3/4; break;
    }
    int stride = gridDim.x * blockDim.x;
    for (int i = blockIdx.x * blockDim.x + threadIdx.x; i < n4; i += stride) {
        float4 v = ((const float4*)src)[i];
        v.x = round_tf32(v.x); v.y = round_tf32(v.y);
        v.z = round_tf32(v.z); v.w = round_tf32(v.w);
        ((float4*)dst)[i] = v;
    }
}

// ---------------- parallel stable descending argsort (rank-based) ------------
__global__ void sort_kernel(const int* __restrict__ s_hlen, const int* __restrict__ o_hlen)
{
    __shared__ int sv[Bq], ov[Bq];
    int t = threadIdx.x;
    int b = t & 511;
    if (t < 512) sv[b] = s_hlen[b]; else ov[b] = o_hlen[b];
    __syncthreads();
    const int* L = (t < 512) ? sv : ov;
    int lv = L[b];
    int r = 0;
    for (int j = 0; j < Bq; j++) {
        int v = L[j];
        r += (v > lv) || (v == lv && j < b);
    }
    if (t < 512) g_sidx[r] = b; else g_oidx[r] = b;
}

// ---------------- gather X = [ent[sid] || ent[rid]] (tf32-rounded) -----------
__global__ void gather_x(const int* __restrict__ trip, const float* __restrict__ ent)
{
    int b = blockIdx.x, z = blockIdx.y;
    float* X = (z ? g_x_o : g_x_s) + (size_t)b * H2;
    int scol = z ? 2 : 0;
    int sid = trip[b * 3 + scol], rid = trip[b * 3 + 1];
    for (int i = threadIdx.x; i < Hh; i += 128) {
        X[i]      = round_tf32(ent[(size_t)sid * Hh + i]);
        X[Hh + i] = round_tf32(ent[(size_t)rid * Hh + i]);
    }
}

// ============ tf32 tensor-core GEMM: C[M,N] = A[M,K] @ W[N,K]^T (+bias) ======
// 256 threads = 8 warps; CTA tile 128x128; warp tile 32x64 (4m x 2n warps),
// 2x8 m16n8k8 frags = 16 independent HMMA per warp per k-tile, 24 LDS (1.5/HMMA).
// Pair-pipelined 6-stage smem ring (48 KB); one wait+sync per PAIR of k-tiles.
// Inputs must be tf32-pre-rounded. Scalar C stores (C may be misaligned).
__device__ __forceinline__
void gemm_tc_body(const float* __restrict__ A, int lda,
                  const float* __restrict__ W, int ldw,
                  const float* __restrict__ bias,
                  float* __restrict__ C, int ldc,
                  int M, int N, int K)
{
    __shared__ float As[6][128][8];
    __shared__ float Ws[6][128][8];

    const int tid  = threadIdx.x;
    const int bm   = blockIdx.y * 128;
    const int bn   = blockIdx.x * 128;
    const int wid  = tid >> 5, lane = tid & 31;
    const int gid  = lane >> 2, tig = lane & 3;
    const int wm   = (wid & 3) * 32;     // 4 m-positions
    const int wn   = (wid >> 2) * 64;    // 2 n-positions

    // ---- staging: both A and W use row = tid>>1, 16B chunk = tid&1 ----
    const int sr = tid >> 1;
    const int sc = tid & 1;
    int rA = bm + sr; if (rA > M - 1) rA = M - 1;
    const float* aSrc = A + (size_t)rA * lda + 4 * sc;
    uint32_t aDst = (uint32_t)__cvta_generic_to_shared(
        &As[0][sr][4 * (sc ^ ((sr >> 2) & 1))]);
    int rW = bn + sr; if (rW > N - 1) rW = N - 1;
    const float* wSrc = W + (size_t)rW * ldw + 4 * sc;
    uint32_t wDst = (uint32_t)__cvta_generic_to_shared(
        &Ws[0][sr][4 * (sc ^ ((sr >> 2) & 1))]);

    const uint32_t A_ST = 128 * 8 * 4;
    const uint32_t W_ST = 128 * 8 * 4;

    const int nt = K >> 3;
    const int np = (nt + 1) >> 1;

    // prologue: pair 0 -> stages {0,1}; pair 1 -> stages {2,3}
    {
        cp16(aDst, aSrc);
        cp16(wDst, wSrc);
        if (1 < nt) {
            cp16(aDst + A_ST, aSrc + 8);
            cp16(wDst + W_ST, wSrc + 8);
        }
        cp_commit();
        if (2 < nt) {
            cp16(aDst + 2 * A_ST, aSrc + 16);
            cp16(wDst + 2 * W_ST, wSrc + 16);
            if (3 < nt) {
                cp16(aDst + 3 * A_ST, aSrc + 24);
                cp16(wDst + 3 * W_ST, wSrc + 24);
            }
        }
        cp_commit();
    }

    float acc[2][8][4];
#pragma unroll
    for (int i = 0; i < 2; i++)
#pragma unroll
        for (int j = 0; j < 8; j++)
#pragma unroll
            for (int e = 0; e < 4; e++) acc[i][j][e] = 0.f;

    const int s   = gid >> 2;
    const int klo = 4 * s + tig;
    const int khi = 4 - 4 * s + tig;

    for (int p = 0; p < np; p++) {
        if (p < np - 1) asm volatile("cp.async.wait_group 1;");
        else            asm volatile("cp.async.wait_group 0;");
        __syncthreads();

        // prefetch pair p+2 into pair-slot (p+2)%3 (consumed at iter p-1, safe)
        {
            int q = p + 2;
            if (q < np) {
                int st = (q - (q / 3) * 3) * 2;     // (q%3)*2
                int kt0 = q * 2;
                cp16(aDst + (uint32_t)st * A_ST, aSrc + kt0 * 8);
                cp16(wDst + (uint32_t)st * W_ST, wSrc + kt0 * 8);
                if (kt0 + 1 < nt) {
                    cp16(aDst + (uint32_t)(st + 1) * A_ST, aSrc + (kt0 + 1) * 8);
                    cp16(wDst + (uint32_t)(st + 1) * W_ST, wSrc + (kt0 + 1) * 8);
                }
            }
            cp_commit();
        }

        // consume the two sub-tiles of pair p
        const int base = (p - (p / 3) * 3) * 2;     // (p%3)*2
#pragma unroll
        for (int sub = 0; sub < 2; sub++) {
            int kt = 2 * p + sub;
            if (kt >= nt) break;
            const int buf = base + sub;
            uint32_t afr[2][4], bfr[8][2];
#pragma unroll
            for (int i = 0; i < 2; i++) {
                int mb = wm + 16 * i + gid;
                afr[i][0] = __float_as_uint(As[buf][mb    ][klo]);
                afr[i][1] = __float_as_uint(As[buf][mb + 8][klo]);
                afr[i][2] = __float_as_uint(As[buf][mb    ][khi]);
                afr[i][3] = __float_as_uint(As[buf][mb + 8][khi]);
            }
#pragma unroll
            for (int j = 0; j < 8; j++) {
                int nb = wn + 8 * j + gid;
                bfr[j][0] = __float_as_uint(Ws[buf][nb][klo]);
                bfr[j][1] = __float_as_uint(Ws[buf][nb][khi]);
            }
#pragma unroll
            for (int i = 0; i < 2; i++)
#pragma unroll
                for (int j = 0; j < 8; j++)
                    mma_tf32(acc[i][j], afr[i], bfr[j]);
        }
    }

    // epilogue (scalar stores — C may be misaligned, e.g. d_out+1)
#pragma unroll
    for (int i = 0; i < 2; i++) {
        int r0 = bm + wm + 16 * i + gid;
        int r1 = r0 + 8;
#pragma unroll
        for (int j = 0; j < 8; j++) {
            int c = bn + wn + 8 * j + 2 * tig;
            if (c < N) {
                float b0 = bias ? bias[c]     : 0.f;
                float b1 = bias ? bias[c + 1] : 0.f;
                if (r0 < M) {
                    C[(size_t)r0 * ldc + c]     = acc[i][j][0] + b0;
                    C[(size_t)r0 * ldc + c + 1] = acc[i][j][1] + b1;
                }
                if (r1 < M) {
                    C[(size_t)r1 * ldc + c]     = acc[i][j][2] + b0;
                    C[(size_t)r1 * ldc + c + 1] = acc[i][j][3] + b1;
                }
            }
        }
    }
}

struct GemmArgs {
    const float* A; int lda;
    const float* W; int ldw;
    const float* bias;
    float* C; int ldc;
};

__global__ __launch_bounds__(256)
void gemm_tc_dual(GemmArgs a0, GemmArgs a1, int M, int N, int K)
{
    const GemmArgs& g = blockIdx.z ? a1 : a0;
    gemm_tc_body(g.A, g.lda, g.W, g.ldw, g.bias, g.C, g.ldc, M, N, K);
}

// ---------------- attention (both streams via blockIdx.y) --------------------
struct AttnArgs {
    const int* neigh; const int* nlen; const int* hlen;
    const float* proj; const float* bias; const float* v;
    float* seq; int scol;
};

__global__ void attn_dual(AttnArgs a0, AttnArgs a1,
                          const int* __restrict__ trip,
                          const float* __restrict__ ent,
                          const float* __restrict__ rel)
{
    const AttnArgs& a = blockIdx.y ? a1 : a0;
    const int bt = blockIdx.x;
    const int b = bt / Tt, t = bt % Tt;
    __shared__ float s_bias[Hh], s_v[Hh];
    __shared__ float s_logit[Nn], s_w[Nn];
    __shared__ int s_nidx[Nn];
    const int tid = threadIdx.x;
    for (int g = tid; g < Hh; g += 256) { s_bias[g] = a.bias[b * Hh + g]; s_v[g] = a.v[g]; }
    for (int n = tid; n < Nn; n += 256) s_nidx[n] = a.neigh[((size_t)b * Tt + t) * Nn + n];
    __syncthreads();
    const int nl = a.nlen[b * Tt + t];
    const int warp = tid >> 5, lane = tid & 31;
    for (int n = warp; n < nl; n += 8) {
        const float* pr = a.proj + (size_t)s_nidx[n] * Hh;
        float acc = 0.f;
        for (int g = lane; g < Hh; g += 32)
            acc += tanh_fast(pr[g] + s_bias[g]) * s_v[g];
        for (int o = 16; o; o >>= 1) acc += __shfl_xor_sync(0xffffffffu, acc, o);
        if (lane == 0) s_logit[n] = acc;
    }
    __syncthreads();
    if (warp == 0) {
        float m = -3.4e38f;
        for (int n = lane; n < nl; n += 32) m = fmaxf(m, s_logit[n]);
        for (int o = 16; o; o >>= 1) m = fmaxf(m, __shfl_xor_sync(0xffffffffu, m, o));
        float s = 0.f;
        for (int n = lane; n < nl; n += 32) { float e = expf(s_logit[n] - m); s_w[n] = e; s += e; }
        for (int o = 16; o; o >>= 1) s += __shfl_xor_sync(0xffffffffu, s, o);
        float inv = 1.f / s;
        for (int n = lane; n < nl; n += 32) s_w[n] *= inv;
    }
    __syncthreads();
    const float msk = (t < a.hlen[b]) ? 1.f : 0.f;
    const int sid = trip[b * 3 + a.scol], rid = trip[b * 3 + 1];
    float* out = a.seq + ((size_t)b * Tt + t) * H3;
    for (int h = tid; h < Hh; h += 256) {
        float acc = 0.f;
        for (int n = 0; n < nl; n++) acc += s_w[n] * ent[(size_t)s_nidx[n] * Hh + h];
        out[h]          = round_tf32(acc * msk);
        out[Hh + h]     = round_tf32(ent[(size_t)sid * Hh + h] * msk);
        out[2 * Hh + h] = round_tf32(rel[(size_t)rid * Hh + h] * msk);
    }
}

// ---------------- fused GRU: whole T-loop in one launch -----------------------
__global__ __launch_bounds__(256)
void gru_fused(const float* __restrict__ Whh_s, const float* __restrict__ bhh_s,
               const float* __restrict__ Whh_o, const float* __restrict__ bhh_o,
               const int* __restrict__ slen, const int* __restrict__ olen)
{
    const int z = blockIdx.y;
    const float* Whh = z ? Whh_o : Whh_s;
    const float* bhh = z ? bhh_o : bhh_s;
    const float* gi  = z ? g_gi_o : g_gi_s;
    float* hout      = z ? g_h_o : g_h_s;
    const int* len   = z ? olen : slen;
    const int b0 = blockIdx.x * 8;
    const int tid = threadIdx.x;

    __shared__ float h_sm[8][Hh];
    __shared__ float gh_sm[8][H3];
    __shared__ int   len_sm[8];

    for (int i = tid; i < 8 * Hh; i += 256) h_sm[i / Hh][i % Hh] = 0.f;
    if (tid < 8) len_sm[tid] = len[b0 + tid];
    __syncthreads();

    for (int t = 0; t < Tt; t++) {
        for (int j = tid; j < H3; j += 256) {
            const float* wrow = Whh + (size_t)j * Hh;
            float acc[8];
#pragma unroll
            for (int b = 0; b < 8; b++) acc[b] = 0.f;
            for (int k = 0; k < Hh; k += 4) {
                float4 w = *(const float4*)(wrow + k);
#pragma unroll
                for (int b = 0; b < 8; b++) {
                    float4 h4 = *(const float4*)&h_sm[b][k];
                    acc[b] += w.x * h4.x + w.y * h4.y + w.z * h4.z + w.w * h4.w;
                }
            }
            float bb = bhh[j];
#pragma unroll
            for (int b = 0; b < 8; b++) gh_sm[b][j] = acc[b] + bb;
        }
        __syncthreads();

        for (int idx = tid; idx < 8 * Hh; idx += 256) {
            int b = idx / Hh, jj = idx % Hh;
            if (t < len_sm[b]) {
                const float* gib = gi + ((size_t)(b0 + b) * Tt + t) * H3;
                float ir = gib[jj], iz = gib[Hh + jj], in = gib[2 * Hh + jj];
                float hr = gh_sm[b][jj], hz = gh_sm[b][Hh + jj], hn = gh_sm[b][2 * Hh + jj];
                float rg = 1.f / (1.f + expf(-(ir + hr)));
                float zg = 1.f / (1.f + expf(-(iz + hz)));
                float ng = tanhf(in + rg * hn);
                h_sm[b][jj] = (1.f - zg) * ng + zg * h_sm[b][jj];
            }
        }
        __syncthreads();
    }

    for (int i = tid; i < 8 * Hh; i += 256)
        hout[(size_t)(b0 + i / Hh) * Hh + (i % Hh)] = h_sm[i / Hh][i % Hh];
}

// ---------------- final feature assembly (tf32-rounded; GEMM input) ----------
__global__ void feat_kernel(const int* __restrict__ trip, const int* __restrict__ idx,
                            int scol, const float* __restrict__ ent,
                            const float* __restrict__ rel, const float* __restrict__ h,
                            float* __restrict__ feat)
{
    int b = blockIdx.x;
    int p = idx[b];
    int sid = trip[p * 3 + scol], rid = trip[p * 3 + 1];
    for (int i = threadIdx.x; i < Hh; i += 256) {
        feat[(size_t)b * H3 + i]        = round_tf32(ent[(size_t)sid * Hh + i]);
        feat[(size_t)b * H3 + Hh + i]   = round_tf32(h[(size_t)p * Hh + i]);
        feat[(size_t)b * H3 + 2*Hh + i] = round_tf32(rel[(size_t)rid * Hh + i]);
    }
}

// ---------------- cross-entropy per-row log-prob of label --------------------
__global__ void ce_kernel(const float* __restrict__ pred, const int* __restrict__ trip,
                          const int* __restrict__ idx, int labcol, float* __restrict__ lp)
{
    int b = blockIdx.x;
    const float* row = pred + (size_t)b * Ee;
    int tid = threadIdx.x;
    int lane = tid & 31, warp = tid >> 5;
    __shared__ float sred[8];

    float m = -3.4e38f;
    for (int i = tid; i < Ee; i += 256) m = fmaxf(m, row[i]);
    for (int o = 16; o; o >>= 1) m = fmaxf(m, __shfl_xor_sync(0xffffffffu, m, o));
    if (lane == 0) sred[warp] = m;
    __syncthreads();
    if (tid == 0) {
        float mm = sred[0];
        for (int i = 1; i < 8; i++) mm = fmaxf(mm, sred[i]);
        sred[0] = mm;
    }
    __syncthreads();
    m = sred[0];
    __syncthreads();

    float s = 0.f;
    for (int i = tid; i < Ee; i += 256) s += expf(row[i] - m);
    for (int o = 16; o; o >>= 1) s += __shfl_xor_sync(0xffffffffu, s, o);
    if (lane == 0) sred[warp] = s;
    __syncthreads();
    if (tid == 0) {
        float st = 0.f;
        for (int i = 0; i < 8; i++) st += sred[i];
        int lab = trip[idx[b] * 3 + labcol];
        lp[b] = row[lab] - m - logf(st);
    }
}

// ---------------- finalize: loss + index outputs ------------------------------
__global__ void finalize_kernel(float* __restrict__ out)
{
    int tid = threadIdx.x;
    if (tid == 0) {
        double a = 0.0, c = 0.0;
        for (int b = 0; b < Bq; b++) { a += (double)g_lp0[b]; c += (double)g_lp1[b]; }
        out[0] = (float)(-(a / (double)Bq) - (c / (double)Bq));
    }
    for (int b = tid; b < Bq; b += blockDim.x) {
        out[1 + 2 * (size_t)BE + b]       = (float)g_oidx[b];
        out[1 + 2 * (size_t)BE + Bq + b]  = (float)g_sidx[b];
    }
}

// ---------------- host-side orchestration ------------------------------------
extern "C" void kernel_launch(void* const* d_in, const int* in_sizes, int n_in,
                              void* d_out, int out_size)
{
    const int*   trip     = (const int*)d_in[0];
    const int*   s_neigh  = (const int*)d_in[1];
    const int*   s_nlen   = (const int*)d_in[2];
    const int*   s_hlen   = (const int*)d_in[3];
    const int*   o_neigh  = (const int*)d_in[4];
    const int*   o_nlen   = (const int*)d_in[5];
    const int*   o_hlen   = (const int*)d_in[6];
    const float* ent      = (const float*)d_in[7];
    const float* rel      = (const float*)d_in[8];
    const float* attn_s_w = (const float*)d_in[9];
    const float* attn_s_b = (const float*)d_in[10];
    const float* v_s      = (const float*)d_in[11];
    const float* attn_o_w = (const float*)d_in[12];
    const float* attn_o_b = (const float*)d_in[13];
    const float* v_o      = (const float*)d_in[14];
    const float* sub_w_ih = (const float*)d_in[15];
    const float* sub_w_hh = (const float*)d_in[16];
    const float* sub_b_ih = (const float*)d_in[17];
    const float* sub_b_hh = (const float*)d_in[18];
    const float* ob_w_ih  = (const float*)d_in[19];
    const float* ob_w_hh  = (const float*)d_in[20];
    const float* ob_b_ih  = (const float*)d_in[21];
    const float* ob_b_hh  = (const float*)d_in[22];
    const float* lin_sub_w = (const float*)d_in[23];
    const float* lin_sub_b = (const float*)d_in[24];
    const float* lin_ob_w  = (const float*)d_in[25];
    const float* lin_ob_b  = (const float*)d_in[26];
    float* out = (float*)d_out;

    float *proj_s, *proj_o, *x_s, *x_o, *bias_s, *bias_o, *seq_s, *seq_o;
    float *gi_s, *gi_o, *h_s, *h_o, *feat_s, *feat_o, *lp0, *lp1;
    float *ent_r, *wa_s, *wa_o, *wih_s, *wih_o, *wlin_s, *wlin_o;
    int *sidx, *oidx;
    cudaGetSymbolAddress((void**)&proj_s, g_proj_s);
    cudaGetSymbolAddress((void**)&proj_o, g_proj_o);
    cudaGetSymbolAddress((void**)&x_s,    g_x_s);
    cudaGetSymbolAddress((void**)&x_o,    g_x_o);
    cudaGetSymbolAddress((void**)&bias_s, g_bias_s);
    cudaGetSymbolAddress((void**)&bias_o, g_bias_o);
    cudaGetSymbolAddress((void**)&seq_s,  g_seq_s);
    cudaGetSymbolAddress((void**)&seq_o,  g_seq_o);
    cudaGetSymbolAddress((void**)&gi_s,   g_gi_s);
    cudaGetSymbolAddress((void**)&gi_o,   g_gi_o);
    cudaGetSymbolAddress((void**)&h_s,    g_h_s);
    cudaGetSymbolAddress((void**)&h_o,    g_h_o);
    cudaGetSymbolAddress((void**)&feat_s, g_feat_s);
    cudaGetSymbolAddress((void**)&feat_o, g_feat_o);
    cudaGetSymbolAddress((void**)&lp0,    g_lp0);
    cudaGetSymbolAddress((void**)&lp1,    g_lp1);
    cudaGetSymbolAddress((void**)&sidx,   g_sidx);
    cudaGetSymbolAddress((void**)&oidx,   g_oidx);
    cudaGetSymbolAddress((void**)&ent_r,  g_ent_r);
    cudaGetSymbolAddress((void**)&wa_s,   g_wa_s);
    cudaGetSymbolAddress((void**)&wa_o,   g_wa_o);
    cudaGetSymbolAddress((void**)&wih_s,  g_wih_s);
    cudaGetSymbolAddress((void**)&wih_o,  g_wih_o);
    cudaGetSymbolAddress((void**)&wlin_s, g_wlin_s);
    cudaGetSymbolAddress((void**)&wlin_o, g_wlin_o);

    // 0) pre-round all static GEMM inputs to tf32
    round_all<<<dim3(256, 7), 256>>>(ent, attn_s_w, attn_o_w,
                                     sub_w_ih, ob_w_ih, lin_sub_w, lin_ob_w);

    // 1) sort + X gather (rounded)
    sort_kernel<<<1, 1024>>>(s_hlen, o_hlen);
    gather_x<<<dim3(Bq, 2), 128>>>(trip, ent);

    // 2) entity projections (dual)  M=Ee,N=Hh,K=Hh
    {
        GemmArgs a0{ent_r, Hh, wa_s, H3, nullptr, proj_s, Hh};
        GemmArgs a1{ent_r, Hh, wa_o, H3, nullptr, proj_o, Hh};
        dim3 g((Hh + 127) / 128, (Ee + 127) / 128, 2);
        gemm_tc_dual<<<g, 256>>>(a0, a1, Ee, Hh, Hh);
    }

    // 3) bias GEMM (dual)  M=Bq,N=Hh,K=2H
    {
        GemmArgs a0{x_s, H2, wa_s + Hh, H3, attn_s_b, bias_s, Hh};
        GemmArgs a1{x_o, H2, wa_o + Hh, H3, attn_o_b, bias_o, Hh};
        dim3 g((Hh + 127) / 128, (Bq + 127) / 128, 2);
        gemm_tc_dual<<<g, 256>>>(a0, a1, Bq, Hh, H2);
    }

    // 4) attention (both streams, one launch)
    {
        AttnArgs a0{s_neigh, s_nlen, s_hlen, proj_s, bias_s, v_s, seq_s, 0};
        AttnArgs a1{o_neigh, o_nlen, o_hlen, proj_o, bias_o, v_o, seq_o, 2};
        attn_dual<<<dim3(Bq * Tt, 2), 256>>>(a0, a1, trip, ent, rel);
    }

    // 5) GRU input gates (dual)  M=B*T,N=3H,K=3H
    {
        GemmArgs a0{seq_s, H3, wih_s, H3, sub_b_ih, gi_s, H3};
        GemmArgs a1{seq_o, H3, wih_o, H3, ob_b_ih,  gi_o, H3};
        dim3 g((H3 + 127) / 128, (Bq * Tt + 127) / 128, 2);
        gemm_tc_dual<<<g, 256>>>(a0, a1, Bq * Tt, H3, H3);
    }

    // 6) fused GRU — whole T-loop, both streams, one launch
    gru_fused<<<dim3(Bq / 8, 2), 256>>>(sub_w_hh, sub_b_hh, ob_w_hh, ob_b_hh,
                                        s_hlen, o_hlen);

    // 7) permuted feature assembly
    feat_kernel<<<Bq, 256>>>(trip, sidx, 0, ent, rel, h_s, feat_s);
    feat_kernel<<<Bq, 256>>>(trip, oidx, 2, ent, rel, h_o, feat_o);

    // 8) prediction GEMMs into d_out (dual)  M=Bq,N=Ee,K=3H
    //    layout: [loss(1) | sub_pred(B*E) | ob_pred(B*E) | o_idx(B) | s_idx(B)]
    {
        GemmArgs a0{feat_s, H3, wlin_s, H3, lin_sub_b, out + 1 + (size_t)BE, Ee};
        GemmArgs a1{feat_o, H3, wlin_o, H3, lin_ob_b,  out + 1,              Ee};
        dim3 g((Ee + 127) / 128, (Bq + 127) / 128, 2);
        gemm_tc_dual<<<g, 256>>>(a0, a1, Bq, Ee, H3);
    }

    // 9) CE log-probs + finalize
    ce_kernel<<<Bq, 256>>>(out + 1 + (size_t)BE, trip, sidx, 2, lp0);
    ce_kernel<<<Bq, 256>>>(out + 1,              trip, oidx, 0, lp1);
    finalize_kernel<<<1, 512>>>(out);
}

// round 15
// speedup vs baseline: 1.0888x; 1.0046x over previous
#include <cuda_runtime.h>
#include <math.h>
#include <stdint.h>

// Problem constants
#define Bq 512
#define Tt 10
#define Nn 50
#define Hh 200
#define Ee 10000
#define Rr 200
#define H3 600
#define H2 400
#define BE (Bq*Ee)

// ---------------- scratch (static __device__, no allocations) ----------------
__device__ float g_proj_s[Ee*Hh];
__device__ float g_proj_o[Ee*Hh];
__device__ float g_x_s[Bq*H2];
__device__ float g_x_o[Bq*H2];
__device__ float g_bias_s[Bq*Hh];
__device__ float g_bias_o[Bq*Hh];
__device__ float g_seq_s[Bq*Tt*H3];
__device__ float g_seq_o[Bq*Tt*H3];
__device__ float g_gi_s[Bq*Tt*H3];
__device__ float g_gi_o[Bq*Tt*H3];
__device__ float g_h_s[Bq*Hh];
__device__ float g_h_o[Bq*Hh];
__device__ float g_feat_s[Bq*H3];
__device__ float g_feat_o[Bq*H3];
__device__ float g_lp0[Bq];
__device__ float g_lp1[Bq];
__device__ int   g_sidx[Bq];
__device__ int   g_oidx[Bq];

// tf32-rounded copies of GEMM inputs (rounded ONCE; GEMM feeds raw bits to MMA)
__device__ float g_ent_r [Ee*Hh];
__device__ float g_wa_s  [Hh*H3];
__device__ float g_wa_o  [Hh*H3];
__device__ float g_wih_s [H3*H3];
__device__ float g_wih_o [H3*H3];
__device__ float g_wlin_s[Ee*H3];
__device__ float g_wlin_o[Ee*H3];

__device__ __forceinline__ float tanh_fast(float x) {
    float y;
    asm("tanh.approx.f32 %0, %1;" : "=f"(y) : "f"(x));
    return y;
}

__device__ __forceinline__ uint32_t cvt_tf32(float x) {
    uint32_t y;
    asm("cvt.rna.tf32.f32 %0, %1;" : "=r"(y) : "f"(x));
    return y;
}
__device__ __forceinline__ float round_tf32(float x) {
    return __uint_as_float(cvt_tf32(x));
}

__device__ __forceinline__ void mma_tf32(float* d, const uint32_t* a, const uint32_t* b) {
    asm volatile(
        "mma.sync.aligned.m16n8k8.row.col.f32.tf32.tf32.f32 "
        "{%0,%1,%2,%3}, {%4,%5,%6,%7}, {%8,%9}, {%0,%1,%2,%3};"
        : "+f"(d[0]), "+f"(d[1]), "+f"(d[2]), "+f"(d[3])
        : "r"(a[0]), "r"(a[1]), "r"(a[2]), "r"(a[3]), "r"(b[0]), "r"(b[1]));
}

__device__ __forceinline__ void cp16(uint32_t dst, const float* src) {
    asm volatile("cp.async.cg.shared.global [%0], [%1], 16;" :: "r"(dst), "l"(src));
}
__device__ __forceinline__ void cp_commit() {
    asm volatile("cp.async.commit_group;");
}

// ---------------- pre-round all static GEMM inputs to tf32 -------------------
__global__ void round_all(const float* __restrict__ ent,
                          const float* __restrict__ wa_s, const float* __restrict__ wa_o,
                          const float* __restrict__ wih_s, const float* __restrict__ wih_o,
                          const float* __restrict__ wlin_s, const float* __restrict__ wlin_o)
{
    const float* src; float* dst; int n4;
    switch (blockIdx.y) {
        case 0: src = ent;    dst = g_ent_r;  n4 = Ee*Hh/4;  break;
        case 1: src = wa_s;   dst = g_wa_s;   n4 = Hh*H3/4;  break;
        case 2: src = wa_o;   dst = g_wa_o;   n4 = Hh*H3/4;  break;
        case 3: src = wih_s;  dst = g_wih_s;  n4 = H3*H3/4;  break;
        case 4: src = wih_o;  dst = g_wih_o;  n4 = H3*H3/4;  break;
        case 5: src = wlin_s; dst = g_wlin_s; n4 = Ee*H3/4;  break;
        default: src = wlin_o; dst = g_wlin_o; n4 = Ee*H3/4; break;
    }
    int stride = gridDim.x * blockDim.x;
    for (int i = blockIdx.x * blockDim.x + threadIdx.x; i < n4; i += stride) {
        float4 v = ((const float4*)src)[i];
        v.x = round_tf32(v.x); v.y = round_tf32(v.y);
        v.z = round_tf32(v.z); v.w = round_tf32(v.w);
        ((float4*)dst)[i] = v;
    }
}

// ---------------- parallel stable descending argsort (rank-based) ------------
__global__ void sort_kernel(const int* __restrict__ s_hlen, const int* __restrict__ o_hlen)
{
    __shared__ int sv[Bq], ov[Bq];
    int t = threadIdx.x;
    int b = t & 511;
    if (t < 512) sv[b] = s_hlen[b]; else ov[b] = o_hlen[b];
    __syncthreads();
    const int* L = (t < 512) ? sv : ov;
    int lv = L[b];
    int r = 0;
    for (int j = 0; j < Bq; j++) {
        int v = L[j];
        r += (v > lv) || (v == lv && j < b);
    }
    if (t < 512) g_sidx[r] = b; else g_oidx[r] = b;
}

// ---------------- gather X = [ent[sid] || ent[rid]] (tf32-rounded) -----------
__global__ void gather_x(const int* __restrict__ trip, const float* __restrict__ ent)
{
    int b = blockIdx.x, z = blockIdx.y;
    float* X = (z ? g_x_o : g_x_s) + (size_t)b * H2;
    int scol = z ? 2 : 0;
    int sid = trip[b * 3 + scol], rid = trip[b * 3 + 1];
    for (int i = threadIdx.x; i < Hh; i += 128) {
        X[i]      = round_tf32(ent[(size_t)sid * Hh + i]);
        X[Hh + i] = round_tf32(ent[(size_t)rid * Hh + i]);
    }
}

// ============ tf32 tensor-core GEMM: C[M,N] = A[M,K] @ W[N,K]^T (+bias) ======
// 256 threads = 8 warps; CTA tile 128x64; warp tile 32x32 = 2x4 m16n8k8.
// DEEP pipeline: 10 smem stages = 5 PAIRS of 8-deep k-tiles, 4 cp.async groups
// in flight (uniform wait_group 3; one commit per iteration keeps count exact).
// Inputs must be tf32-pre-rounded (raw bits fed to MMA). Scalar C stores.
__device__ __forceinline__
void gemm_tc_body(const float* __restrict__ A, int lda,
                  const float* __restrict__ W, int ldw,
                  const float* __restrict__ bias,
                  float* __restrict__ C, int ldc,
                  int M, int N, int K)
{
    __shared__ float As[10][128][8];
    __shared__ float Ws[10][64][8];

    const int tid  = threadIdx.x;
    const int bm   = blockIdx.y * 128;
    const int bn   = blockIdx.x * 64;
    const int wid  = tid >> 5, lane = tid & 31;
    const int gid  = lane >> 2, tig = lane & 3;
    const int wm   = (wid & 3) * 32;
    const int wn   = (wid >> 2) * 32;

    const int sm_r = tid >> 1;
    const int sc   = tid & 1;
    uint32_t aDst = (uint32_t)__cvta_generic_to_shared(
        &As[0][sm_r][4 * (sc ^ ((sm_r >> 2) & 1))]);
    int rA = bm + sm_r; if (rA > M - 1) rA = M - 1;
    const float* aSrc = A + (size_t)rA * lda + 4 * sc;

    uint32_t wDst = 0; const float* wSrc = A;
    const bool doW = (tid < 128);
    if (doW) {
        const int sn = tid >> 1;
        wDst = (uint32_t)__cvta_generic_to_shared(
            &Ws[0][sn][4 * (sc ^ ((sn >> 2) & 1))]);
        int rW = bn + sn; if (rW > N - 1) rW = N - 1;
        wSrc = W + (size_t)rW * ldw + 4 * sc;
    }
    const uint32_t A_ST = 128 * 8 * 4;
    const uint32_t W_ST = 64 * 8 * 4;

    const int nt = K >> 3;
    const int np = (nt + 1) >> 1;

    // prologue: pairs 0..3 -> stages {0..7}, one commit per pair (group q = pair q)
#pragma unroll
    for (int q = 0; q < 4; q++) {
        int kt0 = q * 2;
        if (kt0 < nt) {
            cp16(aDst + (uint32_t)(2 * q) * A_ST, aSrc + kt0 * 8);
            if (doW) cp16(wDst + (uint32_t)(2 * q) * W_ST, wSrc + kt0 * 8);
            if (kt0 + 1 < nt) {
                cp16(aDst + (uint32_t)(2 * q + 1) * A_ST, aSrc + (kt0 + 1) * 8);
                if (doW) cp16(wDst + (uint32_t)(2 * q + 1) * W_ST, wSrc + (kt0 + 1) * 8);
            }
        }
        cp_commit();
    }

    float acc[2][4][4];
#pragma unroll
    for (int i = 0; i < 2; i++)
#pragma unroll
        for (int j = 0; j < 4; j++)
#pragma unroll
            for (int e = 0; e < 4; e++) acc[i][j][e] = 0.f;

    const int s   = gid >> 2;
    const int klo = 4 * s + tig;
    const int khi = 4 - 4 * s + tig;

    for (int p = 0; p < np; p++) {
        // group for pair p is the (p+1)-th of (p+4) committed -> <=3 outstanding
        // guarantees it is complete (one commit happens every iteration).
        asm volatile("cp.async.wait_group 3;");
        __syncthreads();

        // prefetch pair p+4 into slot (p+4)%5 (stages 2*slot, 2*slot+1);
        // that slot was consumed at iteration p-1, behind this barrier -> safe.
        {
            int q = p + 4;
            if (q < np) {
                int slot = q % 5;
                int kt0 = q * 2;
                cp16(aDst + (uint32_t)(2 * slot) * A_ST, aSrc + kt0 * 8);
                if (doW) cp16(wDst + (uint32_t)(2 * slot) * W_ST, wSrc + kt0 * 8);
                if (kt0 + 1 < nt) {
                    cp16(aDst + (uint32_t)(2 * slot + 1) * A_ST, aSrc + (kt0 + 1) * 8);
                    if (doW) cp16(wDst + (uint32_t)(2 * slot + 1) * W_ST, wSrc + (kt0 + 1) * 8);
                }
            }
            cp_commit();
        }

        // consume the two sub-tiles of pair p
        const int base = (p % 5) * 2;
#pragma unroll
        for (int sub = 0; sub < 2; sub++) {
            int kt = 2 * p + sub;
            if (kt >= nt) break;
            const int buf = base + sub;
            uint32_t afr[2][4], bfr[4][2];
#pragma unroll
            for (int i = 0; i < 2; i++) {
                int mb = wm + 16 * i + gid;
                afr[i][0] = __float_as_uint(As[buf][mb    ][klo]);
                afr[i][1] = __float_as_uint(As[buf][mb + 8][klo]);
                afr[i][2] = __float_as_uint(As[buf][mb    ][khi]);
                afr[i][3] = __float_as_uint(As[buf][mb + 8][khi]);
            }
#pragma unroll
            for (int j = 0; j < 4; j++) {
                int nb = wn + 8 * j + gid;
                bfr[j][0] = __float_as_uint(Ws[buf][nb][klo]);
                bfr[j][1] = __float_as_uint(Ws[buf][nb][khi]);
            }
#pragma unroll
            for (int i = 0; i < 2; i++)
#pragma unroll
                for (int j = 0; j < 4; j++)
                    mma_tf32(acc[i][j], afr[i], bfr[j]);
        }
    }

    // epilogue (scalar stores — C may be misaligned, e.g. d_out+1)
#pragma unroll
    for (int i = 0; i < 2; i++) {
        int r0 = bm + wm + 16 * i + gid;
        int r1 = r0 + 8;
#pragma unroll
        for (int j = 0; j < 4; j++) {
            int c = bn + wn + 8 * j + 2 * tig;
            if (c < N) {
                float b0 = bias ? bias[c]     : 0.f;
                float b1 = bias ? bias[c + 1] : 0.f;
                if (r0 < M) {
                    C[(size_t)r0 * ldc + c]     = acc[i][j][0] + b0;
                    C[(size_t)r0 * ldc + c + 1] = acc[i][j][1] + b1;
                }
                if (r1 < M) {
                    C[(size_t)r1 * ldc + c]     = acc[i][j][2] + b0;
                    C[(size_t)r1 * ldc + c + 1] = acc[i][j][3] + b1;
                }
            }
        }
    }
}

struct GemmArgs {
    const float* A; int lda;
    const float* W; int ldw;
    const float* bias;
    float* C; int ldc;
};

__global__ __launch_bounds__(256)
void gemm_tc_dual(GemmArgs a0, GemmArgs a1, int M, int N, int K)
{
    const GemmArgs& g = blockIdx.z ? a1 : a0;
    gemm_tc_body(g.A, g.lda, g.W, g.ldw, g.bias, g.C, g.ldc, M, N, K);
}

// ---------------- attention + softmax + weighted sum + seq assembly ----------
__global__ void attn_kernel(const int* __restrict__ neigh, const int* __restrict__ nlen,
                            const int* __restrict__ hlen, const int* __restrict__ trip,
                            int scol,
                            const float* __restrict__ ent, const float* __restrict__ rel,
                            const float* __restrict__ proj, const float* __restrict__ bias,
                            const float* __restrict__ v, float* __restrict__ seq)
{
    const int bt = blockIdx.x;
    const int b = bt / Tt, t = bt % Tt;
    __shared__ float s_bias[Hh], s_v[Hh];
    __shared__ float s_logit[Nn], s_w[Nn];
    __shared__ int s_nidx[Nn];
    const int tid = threadIdx.x;
    for (int g = tid; g < Hh; g += 256) { s_bias[g] = bias[b * Hh + g]; s_v[g] = v[g]; }
    for (int n = tid; n < Nn; n += 256) s_nidx[n] = neigh[((size_t)b * Tt + t) * Nn + n];
    __syncthreads();
    const int nl = nlen[b * Tt + t];
    const int warp = tid >> 5, lane = tid & 31;
    for (int n = warp; n < nl; n += 8) {
        const float* pr = proj + (size_t)s_nidx[n] * Hh;
        float acc = 0.f;
        for (int g = lane; g < Hh; g += 32)
            acc += tanh_fast(pr[g] + s_bias[g]) * s_v[g];
        for (int o = 16; o; o >>= 1) acc += __shfl_xor_sync(0xffffffffu, acc, o);
        if (lane == 0) s_logit[n] = acc;
    }
    __syncthreads();
    if (warp == 0) {
        float m = -3.4e38f;
        for (int n = lane; n < nl; n += 32) m = fmaxf(m, s_logit[n]);
        for (int o = 16; o; o >>= 1) m = fmaxf(m, __shfl_xor_sync(0xffffffffu, m, o));
        float s = 0.f;
        for (int n = lane; n < nl; n += 32) { float e = expf(s_logit[n] - m); s_w[n] = e; s += e; }
        for (int o = 16; o; o >>= 1) s += __shfl_xor_sync(0xffffffffu, s, o);
        float inv = 1.f / s;
        for (int n = lane; n < nl; n += 32) s_w[n] *= inv;
    }
    __syncthreads();
    const float msk = (t < hlen[b]) ? 1.f : 0.f;
    const int sid = trip[b * 3 + scol], rid = trip[b * 3 + 1];
    float* out = seq + ((size_t)b * Tt + t) * H3;
    for (int h = tid; h < Hh; h += 256) {
        float acc = 0.f;
        for (int n = 0; n < nl; n++) acc += s_w[n] * ent[(size_t)s_nidx[n] * Hh + h];
        out[h]          = round_tf32(acc * msk);
        out[Hh + h]     = round_tf32(ent[(size_t)sid * Hh + h] * msk);
        out[2 * Hh + h] = round_tf32(rel[(size_t)rid * Hh + h] * msk);
    }
}

// ---------------- fused GRU: whole T-loop in one launch -----------------------
__global__ __launch_bounds__(256)
void gru_fused(const float* __restrict__ Whh_s, const float* __restrict__ bhh_s,
               const float* __restrict__ Whh_o, const float* __restrict__ bhh_o,
               const int* __restrict__ slen, const int* __restrict__ olen)
{
    const int z = blockIdx.y;
    const float* Whh = z ? Whh_o : Whh_s;
    const float* bhh = z ? bhh_o : bhh_s;
    const float* gi  = z ? g_gi_o : g_gi_s;
    float* hout      = z ? g_h_o : g_h_s;
    const int* len   = z ? olen : slen;
    const int b0 = blockIdx.x * 8;
    const int tid = threadIdx.x;

    __shared__ float h_sm[8][Hh];
    __shared__ float gh_sm[8][H3];
    __shared__ int   len_sm[8];

    for (int i = tid; i < 8 * Hh; i += 256) h_sm[i / Hh][i % Hh] = 0.f;
    if (tid < 8) len_sm[tid] = len[b0 + tid];
    __syncthreads();

    for (int t = 0; t < Tt; t++) {
        for (int j = tid; j < H3; j += 256) {
            const float* wrow = Whh + (size_t)j * Hh;
            float acc[8];
#pragma unroll
            for (int b = 0; b < 8; b++) acc[b] = 0.f;
            for (int k = 0; k < Hh; k += 4) {
                float4 w = *(const float4*)(wrow + k);
#pragma unroll
                for (int b = 0; b < 8; b++) {
                    float4 h4 = *(const float4*)&h_sm[b][k];
                    acc[b] += w.x * h4.x + w.y * h4.y + w.z * h4.z + w.w * h4.w;
                }
            }
            float bb = bhh[j];
#pragma unroll
            for (int b = 0; b < 8; b++) gh_sm[b][j] = acc[b] + bb;
        }
        __syncthreads();

        for (int idx = tid; idx < 8 * Hh; idx += 256) {
            int b = idx / Hh, jj = idx % Hh;
            if (t < len_sm[b]) {
                const float* gib = gi + ((size_t)(b0 + b) * Tt + t) * H3;
                float ir = gib[jj], iz = gib[Hh + jj], in = gib[2 * Hh + jj];
                float hr = gh_sm[b][jj], hz = gh_sm[b][Hh + jj], hn = gh_sm[b][2 * Hh + jj];
                float rg = 1.f / (1.f + expf(-(ir + hr)));
                float zg = 1.f / (1.f + expf(-(iz + hz)));
                float ng = tanhf(in + rg * hn);
                h_sm[b][jj] = (1.f - zg) * ng + zg * h_sm[b][jj];
            }
        }
        __syncthreads();
    }

    for (int i = tid; i < 8 * Hh; i += 256)
        hout[(size_t)(b0 + i / Hh) * Hh + (i % Hh)] = h_sm[i / Hh][i % Hh];
}

// ---------------- final feature assembly (tf32-rounded; GEMM input) ----------
__global__ void feat_kernel(const int* __restrict__ trip, const int* __restrict__ idx,
                            int scol, const float* __restrict__ ent,
                            const float* __restrict__ rel, const float* __restrict__ h,
                            float* __restrict__ feat)
{
    int b = blockIdx.x;
    int p = idx[b];
    int sid = trip[p * 3 + scol], rid = trip[p * 3 + 1];
    for (int i = threadIdx.x; i < Hh; i += 256) {
        feat[(size_t)b * H3 + i]        = round_tf32(ent[(size_t)sid * Hh + i]);
        feat[(size_t)b * H3 + Hh + i]   = round_tf32(h[(size_t)p * Hh + i]);
        feat[(size_t)b * H3 + 2*Hh + i] = round_tf32(rel[(size_t)rid * Hh + i]);
    }
}

// ---------------- cross-entropy: single-pass online softmax ------------------
__global__ void ce_kernel(const float* __restrict__ pred, const int* __restrict__ trip,
                          const int* __restrict__ idx, int labcol, float* __restrict__ lp)
{
    int b = blockIdx.x;
    const float* row = pred + (size_t)b * Ee;
    int tid = threadIdx.x;
    int lane = tid & 31, warp = tid >> 5;
    __shared__ float smax[8], ssum[8];

    // per-thread online (max, sum)
    float m = -3.4e38f, s = 0.f;
    for (int i = tid; i < Ee; i += 256) {
        float v = row[i];
        float nm = fmaxf(m, v);
        s = s * expf(m - nm) + expf(v - nm);
        m = nm;
    }
    // warp combine
    for (int o = 16; o; o >>= 1) {
        float mo = __shfl_xor_sync(0xffffffffu, m, o);
        float so = __shfl_xor_sync(0xffffffffu, s, o);
        float nm = fmaxf(m, mo);
        s = s * expf(m - nm) + so * expf(mo - nm);
        m = nm;
    }
    if (lane == 0) { smax[warp] = m; ssum[warp] = s; }
    __syncthreads();
    if (tid == 0) {
        float mm = smax[0], st = ssum[0];
        for (int i = 1; i < 8; i++) {
            float nm = fmaxf(mm, smax[i]);
            st = st * expf(mm - nm) + ssum[i] * expf(smax[i] - nm);
            mm = nm;
        }
        int lab = trip[idx[b] * 3 + labcol];
        lp[b] = row[lab] - mm - logf(st);
    }
}

// ---------------- finalize: loss + index outputs ------------------------------
__global__ void finalize_kernel(float* __restrict__ out)
{
    int tid = threadIdx.x;
    if (tid == 0) {
        double a = 0.0, c = 0.0;
        for (int b = 0; b < Bq; b++) { a += (double)g_lp0[b]; c += (double)g_lp1[b]; }
        out[0] = (float)(-(a / (double)Bq) - (c / (double)Bq));
    }
    for (int b = tid; b < Bq; b += blockDim.x) {
        out[1 + 2 * (size_t)BE + b]       = (float)g_oidx[b];
        out[1 + 2 * (size_t)BE + Bq + b]  = (float)g_sidx[b];
    }
}

// ---------------- host-side orchestration ------------------------------------
extern "C" void kernel_launch(void* const* d_in, const int* in_sizes, int n_in,
                              void* d_out, int out_size)
{
    const int*   trip     = (const int*)d_in[0];
    const int*   s_neigh  = (const int*)d_in[1];
    const int*   s_nlen   = (const int*)d_in[2];
    const int*   s_hlen   = (const int*)d_in[3];
    const int*   o_neigh  = (const int*)d_in[4];
    const int*   o_nlen   = (const int*)d_in[5];
    const int*   o_hlen   = (const int*)d_in[6];
    const float* ent      = (const float*)d_in[7];
    const float* rel      = (const float*)d_in[8];
    const float* attn_s_w = (const float*)d_in[9];
    const float* attn_s_b = (const float*)d_in[10];
    const float* v_s      = (const float*)d_in[11];
    const float* attn_o_w = (const float*)d_in[12];
    const float* attn_o_b = (const float*)d_in[13];
    const float* v_o      = (const float*)d_in[14];
    const float* sub_w_ih = (const float*)d_in[15];
    const float* sub_w_hh = (const float*)d_in[16];
    const float* sub_b_ih = (const float*)d_in[17];
    const float* sub_b_hh = (const float*)d_in[18];
    const float* ob_w_ih  = (const float*)d_in[19];
    const float* ob_w_hh  = (const float*)d_in[20];
    const float* ob_b_ih  = (const float*)d_in[21];
    const float* ob_b_hh  = (const float*)d_in[22];
    const float* lin_sub_w = (const float*)d_in[23];
    const float* lin_sub_b = (const float*)d_in[24];
    const float* lin_ob_w  = (const float*)d_in[25];
    const float* lin_ob_b  = (const float*)d_in[26];
    float* out = (float*)d_out;

    float *proj_s, *proj_o, *x_s, *x_o, *bias_s, *bias_o, *seq_s, *seq_o;
    float *gi_s, *gi_o, *h_s, *h_o, *feat_s, *feat_o, *lp0, *lp1;
    float *ent_r, *wa_s, *wa_o, *wih_s, *wih_o, *wlin_s, *wlin_o;
    int *sidx, *oidx;
    cudaGetSymbolAddress((void**)&proj_s, g_proj_s);
    cudaGetSymbolAddress((void**)&proj_o, g_proj_o);
    cudaGetSymbolAddress((void**)&x_s,    g_x_s);
    cudaGetSymbolAddress((void**)&x_o,    g_x_o);
    cudaGetSymbolAddress((void**)&bias_s, g_bias_s);
    cudaGetSymbolAddress((void**)&bias_o, g_bias_o);
    cudaGetSymbolAddress((void**)&seq_s,  g_seq_s);
    cudaGetSymbolAddress((void**)&seq_o,  g_seq_o);
    cudaGetSymbolAddress((void**)&gi_s,   g_gi_s);
    cudaGetSymbolAddress((void**)&gi_o,   g_gi_o);
    cudaGetSymbolAddress((void**)&h_s,    g_h_s);
    cudaGetSymbolAddress((void**)&h_o,    g_h_o);
    cudaGetSymbolAddress((void**)&feat_s, g_feat_s);
    cudaGetSymbolAddress((void**)&feat_o, g_feat_o);
    cudaGetSymbolAddress((void**)&lp0,    g_lp0);
    cudaGetSymbolAddress((void**)&lp1,    g_lp1);
    cudaGetSymbolAddress((void**)&sidx,   g_sidx);
    cudaGetSymbolAddress((void**)&oidx,   g_oidx);
    cudaGetSymbolAddress((void**)&ent_r,  g_ent_r);
    cudaGetSymbolAddress((void**)&wa_s,   g_wa_s);
    cudaGetSymbolAddress((void**)&wa_o,   g_wa_o);
    cudaGetSymbolAddress((void**)&wih_s,  g_wih_s);
    cudaGetSymbolAddress((void**)&wih_o,  g_wih_o);
    cudaGetSymbolAddress((void**)&wlin_s, g_wlin_s);
    cudaGetSymbolAddress((void**)&wlin_o, g_wlin_o);

    // 0) pre-round all static GEMM inputs to tf32
    round_all<<<dim3(256, 7), 256>>>(ent, attn_s_w, attn_o_w,
                                     sub_w_ih, ob_w_ih, lin_sub_w, lin_ob_w);

    // 1) sort + X gather (rounded)
    sort_kernel<<<1, 1024>>>(s_hlen, o_hlen);
    gather_x<<<dim3(Bq, 2), 128>>>(trip, ent);

    // 2) entity projections (dual)  M=Ee,N=Hh,K=Hh
    {
        GemmArgs a0{ent_r, Hh, wa_s, H3, nullptr, proj_s, Hh};
        GemmArgs a1{ent_r, Hh, wa_o, H3, nullptr, proj_o, Hh};
        dim3 g((Hh + 63) / 64, (Ee + 127) / 128, 2);
        gemm_tc_dual<<<g, 256>>>(a0, a1, Ee, Hh, Hh);
    }

    // 3) bias GEMM (dual)  M=Bq,N=Hh,K=2H
    {
        GemmArgs a0{x_s, H2, wa_s + Hh, H3, attn_s_b, bias_s, Hh};
        GemmArgs a1{x_o, H2, wa_o + Hh, H3, attn_o_b, bias_o, Hh};
        dim3 g((Hh + 63) / 64, (Bq + 127) / 128, 2);
        gemm_tc_dual<<<g, 256>>>(a0, a1, Bq, Hh, H2);
    }

    // 4) attention + softmax + weighted neighbor sum + seq assembly
    attn_kernel<<<Bq * Tt, 256>>>(s_neigh, s_nlen, s_hlen, trip, 0, ent, rel,
                                  proj_s, bias_s, v_s, seq_s);
    attn_kernel<<<Bq * Tt, 256>>>(o_neigh, o_nlen, o_hlen, trip, 2, ent, rel,
                                  proj_o, bias_o, v_o, seq_o);

    // 5) GRU input gates (dual)  M=B*T,N=3H,K=3H
    {
        GemmArgs a0{seq_s, H3, wih_s, H3, sub_b_ih, gi_s, H3};
        GemmArgs a1{seq_o, H3, wih_o, H3, ob_b_ih,  gi_o, H3};
        dim3 g((H3 + 63) / 64, (Bq * Tt + 127) / 128, 2);
        gemm_tc_dual<<<g, 256>>>(a0, a1, Bq * Tt, H3, H3);
    }

    // 6) fused GRU — whole T-loop, both streams, one launch
    gru_fused<<<dim3(Bq / 8, 2), 256>>>(sub_w_hh, sub_b_hh, ob_w_hh, ob_b_hh,
                                        s_hlen, o_hlen);

    // 7) permuted feature assembly
    feat_kernel<<<Bq, 256>>>(trip, sidx, 0, ent, rel, h_s, feat_s);
    feat_kernel<<<Bq, 256>>>(trip, oidx, 2, ent, rel, h_o, feat_o);

    // 8) prediction GEMMs into d_out (dual)  M=Bq,N=Ee,K=3H
    //    layout: [loss(1) | sub_pred(B*E) | ob_pred(B*E) | o_idx(B) | s_idx(B)]
    {
        GemmArgs a0{feat_s, H3, wlin_s, H3, lin_sub_b, out + 1 + (size_t)BE, Ee};
        GemmArgs a1{feat_o, H3, wlin_o, H3, lin_ob_b,  out + 1,              Ee};
        dim3 g((Ee + 63) / 64, (Bq + 127) / 128, 2);
        gemm_tc_dual<<<g, 256>>>(a0, a1, Bq, Ee, H3);
    }

    // 9) CE log-probs + finalize
    ce_kernel<<<Bq, 256>>>(out + 1 + (size_t)BE, trip, sidx, 2, lp0);
    ce_kernel<<<Bq, 256>>>(out + 1,              trip, oidx, 0, lp1);
    finalize_kernel<<<1, 512>>>(out);
}

// round 16
// speedup vs baseline: 1.1267x; 1.0348x over previous
#include <cuda_runtime.h>
#include <math.h>
#include <stdint.h>

// Problem constants
#define Bq 512
#define Tt 10
#define Nn 50
#define Hh 200
#define Ee 10000
#define Rr 200
#define H3 600
#define H2 400
#define BE (Bq*Ee)

// ---------------- scratch (static __device__, no allocations) ----------------
__device__ float g_proj_s[Ee*Hh];
__device__ float g_proj_o[Ee*Hh];
__device__ float g_x_s[Bq*H2];
__device__ float g_x_o[Bq*H2];
__device__ float g_bias_s[Bq*Hh];
__device__ float g_bias_o[Bq*Hh];
__device__ float g_seq_s[Bq*Tt*H3];
__device__ float g_seq_o[Bq*Tt*H3];
__device__ float g_gi_s[Bq*Tt*H3];
__device__ float g_gi_o[Bq*Tt*H3];
__device__ float g_h_s[Bq*Hh];
__device__ float g_h_o[Bq*Hh];
__device__ float g_feat_s[Bq*H3];
__device__ float g_feat_o[Bq*H3];
__device__ float g_lp0[Bq];
__device__ float g_lp1[Bq];
__device__ int   g_sidx[Bq];
__device__ int   g_oidx[Bq];

// tf32-rounded copies of GEMM inputs (rounded ONCE; GEMM feeds raw bits to MMA)
__device__ float g_ent_r [Ee*Hh];
__device__ float g_wa_s  [Hh*H3];
__device__ float g_wa_o  [Hh*H3];
__device__ float g_wih_s [H3*H3];
__device__ float g_wih_o [H3*H3];
__device__ float g_wlin_s[Ee*H3];
__device__ float g_wlin_o[Ee*H3];

__device__ __forceinline__ float tanh_fast(float x) {
    float y;
    asm("tanh.approx.f32 %0, %1;" : "=f"(y) : "f"(x));
    return y;
}

__device__ __forceinline__ uint32_t cvt_tf32(float x) {
    uint32_t y;
    asm("cvt.rna.tf32.f32 %0, %1;" : "=r"(y) : "f"(x));
    return y;
}
__device__ __forceinline__ float round_tf32(float x) {
    return __uint_as_float(cvt_tf32(x));
}

__device__ __forceinline__ void mma_tf32(float* d, const uint32_t* a, const uint32_t* b) {
    asm volatile(
        "mma.sync.aligned.m16n8k8.row.col.f32.tf32.tf32.f32 "
        "{%0,%1,%2,%3}, {%4,%5,%6,%7}, {%8,%9}, {%0,%1,%2,%3};"
        : "+f"(d[0]), "+f"(d[1]), "+f"(d[2]), "+f"(d[3])
        : "r"(a[0]), "r"(a[1]), "r"(a[2]), "r"(a[3]), "r"(b[0]), "r"(b[1]));
}

__device__ __forceinline__ void cp16(uint32_t dst, const float* src) {
    asm volatile("cp.async.cg.shared.global [%0], [%1], 16;" :: "r"(dst), "l"(src));
}
__device__ __forceinline__ void cp_commit() {
    asm volatile("cp.async.commit_group;");
}

// ---------------- pre-round all static GEMM inputs to tf32 -------------------
__global__ void round_all(const float* __restrict__ ent,
                          const float* __restrict__ wa_s, const float* __restrict__ wa_o,
                          const float* __restrict__ wih_s, const float* __restrict__ wih_o,
                          const float* __restrict__ wlin_s, const float* __restrict__ wlin_o)
{
    const float* src; float* dst; int n4;
    switch (blockIdx.y) {
        case 0: src = ent;    dst = g_ent_r;  n4 = Ee*Hh/4;  break;
        case 1: src = wa_s;   dst = g_wa_s;   n4 = Hh*H3/4;  break;
        case 2: src = wa_o;   dst = g_wa_o;   n4 = Hh*H3/4;  break;
        case 3: src = wih_s;  dst = g_wih_s;  n4 = H3*H3/4;  break;
        case 4: src = wih_o;  dst = g_wih_o;  n4 = H3*H3/4;  break;
        case 5: src = wlin_s; dst = g_wlin_s; n4 = Ee*H3/4;  break;
        default: src = wlin_o; dst = g_wlin_o; n4 = Ee*H3/4; break;
    }
    int stride = gridDim.x * blockDim.x;
    for (int i = blockIdx.x * blockDim.x + threadIdx.x; i < n4; i += stride) {
        float4 v = ((const float4*)src)[i];
        v.x = round_tf32(v.x); v.y = round_tf32(v.y);
        v.z = round_tf32(v.z); v.w = round_tf32(v.w);
        ((float4*)dst)[i] = v;
    }
}

// ---------------- parallel stable descending argsort (rank-based) ------------
__global__ void sort_kernel(const int* __restrict__ s_hlen, const int* __restrict__ o_hlen)
{
    __shared__ int sv[Bq], ov[Bq];
    int t = threadIdx.x;
    int b = t & 511;
    if (t < 512) sv[b] = s_hlen[b]; else ov[b] = o_hlen[b];
    __syncthreads();
    const int* L = (t < 512) ? sv : ov;
    int lv = L[b];
    int r = 0;
    for (int j = 0; j < Bq; j++) {
        int v = L[j];
        r += (v > lv) || (v == lv && j < b);
    }
    if (t < 512) g_sidx[r] = b; else g_oidx[r] = b;
}

// ---------------- gather X = [ent[sid] || ent[rid]] (tf32-rounded) -----------
__global__ void gather_x(const int* __restrict__ trip, const float* __restrict__ ent)
{
    int b = blockIdx.x, z = blockIdx.y;
    float* X = (z ? g_x_o : g_x_s) + (size_t)b * H2;
    int scol = z ? 2 : 0;
    int sid = trip[b * 3 + scol], rid = trip[b * 3 + 1];
    for (int i = threadIdx.x; i < Hh; i += 128) {
        X[i]      = round_tf32(ent[(size_t)sid * Hh + i]);
        X[Hh + i] = round_tf32(ent[(size_t)rid * Hh + i]);
    }
}

// ============ tf32 tensor-core GEMM: C[M,N] = A[M,K] @ W[N,K]^T (+bias) ======
// R12 champion: 256 threads / 8 warps; CTA tile 128x64; warp tile 32x32.
// Pair-pipelined 6-stage smem ring; one wait+sync per PAIR of 8-deep k-tiles.
// Inputs must be tf32-pre-rounded (raw bits to MMA). Scalar C stores.
__device__ __forceinline__
void gemm_tc_body(const float* __restrict__ A, int lda,
                  const float* __restrict__ W, int ldw,
                  const float* __restrict__ bias,
                  float* __restrict__ C, int ldc,
                  int M, int N, int K)
{
    __shared__ float As[6][128][8];
    __shared__ float Ws[6][64][8];

    const int tid  = threadIdx.x;
    const int bm   = blockIdx.y * 128;
    const int bn   = blockIdx.x * 64;
    const int wid  = tid >> 5, lane = tid & 31;
    const int gid  = lane >> 2, tig = lane & 3;
    const int wm   = (wid & 3) * 32;
    const int wn   = (wid >> 2) * 32;

    const int sm_r = tid >> 1;
    const int sc   = tid & 1;
    uint32_t aDst = (uint32_t)__cvta_generic_to_shared(
        &As[0][sm_r][4 * (sc ^ ((sm_r >> 2) & 1))]);
    int rA = bm + sm_r; if (rA > M - 1) rA = M - 1;
    const float* aSrc = A + (size_t)rA * lda + 4 * sc;

    uint32_t wDst = 0; const float* wSrc = A;
    const bool doW = (tid < 128);
    if (doW) {
        const int sn = tid >> 1;
        wDst = (uint32_t)__cvta_generic_to_shared(
            &Ws[0][sn][4 * (sc ^ ((sn >> 2) & 1))]);
        int rW = bn + sn; if (rW > N - 1) rW = N - 1;
        wSrc = W + (size_t)rW * ldw + 4 * sc;
    }
    const uint32_t A_ST = 128 * 8 * 4;
    const uint32_t W_ST = 64 * 8 * 4;

    const int nt = K >> 3;
    const int np = (nt + 1) >> 1;

    // prologue: pair 0 -> stages {0,1}; pair 1 -> stages {2,3}
    {
        cp16(aDst, aSrc);
        if (doW) cp16(wDst, wSrc);
        if (1 < nt) {
            cp16(aDst + A_ST, aSrc + 8);
            if (doW) cp16(wDst + W_ST, wSrc + 8);
        }
        cp_commit();
        if (2 < nt) {
            cp16(aDst + 2 * A_ST, aSrc + 16);
            if (doW) cp16(wDst + 2 * W_ST, wSrc + 16);
            if (3 < nt) {
                cp16(aDst + 3 * A_ST, aSrc + 24);
                if (doW) cp16(wDst + 3 * W_ST, wSrc + 24);
            }
        }
        cp_commit();
    }

    float acc[2][4][4];
#pragma unroll
    for (int i = 0; i < 2; i++)
#pragma unroll
        for (int j = 0; j < 4; j++)
#pragma unroll
            for (int e = 0; e < 4; e++) acc[i][j][e] = 0.f;

    const int s   = gid >> 2;
    const int klo = 4 * s + tig;
    const int khi = 4 - 4 * s + tig;

    for (int p = 0; p < np; p++) {
        if (p < np - 1) asm volatile("cp.async.wait_group 1;");
        else            asm volatile("cp.async.wait_group 0;");
        __syncthreads();

        // prefetch pair p+2 into pair-slot (p+2)%3 (consumed at iter p-1, safe)
        {
            int q = p + 2;
            if (q < np) {
                int st = (q - (q / 3) * 3) * 2;     // (q%3)*2
                int kt0 = q * 2;
                cp16(aDst + (uint32_t)st * A_ST, aSrc + kt0 * 8);
                if (doW) cp16(wDst + (uint32_t)st * W_ST, wSrc + kt0 * 8);
                if (kt0 + 1 < nt) {
                    cp16(aDst + (uint32_t)(st + 1) * A_ST, aSrc + (kt0 + 1) * 8);
                    if (doW) cp16(wDst + (uint32_t)(st + 1) * W_ST, wSrc + (kt0 + 1) * 8);
                }
            }
            cp_commit();
        }

        // consume the two sub-tiles of pair p
        const int base = (p - (p / 3) * 3) * 2;     // (p%3)*2
#pragma unroll
        for (int sub = 0; sub < 2; sub++) {
            int kt = 2 * p + sub;
            if (kt >= nt) break;
            const int buf = base + sub;
            uint32_t afr[2][4], bfr[4][2];
#pragma unroll
            for (int i = 0; i < 2; i++) {
                int mb = wm + 16 * i + gid;
                afr[i][0] = __float_as_uint(As[buf][mb    ][klo]);
                afr[i][1] = __float_as_uint(As[buf][mb + 8][klo]);
                afr[i][2] = __float_as_uint(As[buf][mb    ][khi]);
                afr[i][3] = __float_as_uint(As[buf][mb + 8][khi]);
            }
#pragma unroll
            for (int j = 0; j < 4; j++) {
                int nb = wn + 8 * j + gid;
                bfr[j][0] = __float_as_uint(Ws[buf][nb][klo]);
                bfr[j][1] = __float_as_uint(Ws[buf][nb][khi]);
            }
#pragma unroll
            for (int i = 0; i < 2; i++)
#pragma unroll
                for (int j = 0; j < 4; j++)
                    mma_tf32(acc[i][j], afr[i], bfr[j]);
        }
    }

    // epilogue (scalar stores — C may be misaligned, e.g. d_out+1)
#pragma unroll
    for (int i = 0; i < 2; i++) {
        int r0 = bm + wm + 16 * i + gid;
        int r1 = r0 + 8;
#pragma unroll
        for (int j = 0; j < 4; j++) {
            int c = bn + wn + 8 * j + 2 * tig;
            if (c < N) {
                float b0 = bias ? bias[c]     : 0.f;
                float b1 = bias ? bias[c + 1] : 0.f;
                if (r0 < M) {
                    C[(size_t)r0 * ldc + c]     = acc[i][j][0] + b0;
                    C[(size_t)r0 * ldc + c + 1] = acc[i][j][1] + b1;
                }
                if (r1 < M) {
                    C[(size_t)r1 * ldc + c]     = acc[i][j][2] + b0;
                    C[(size_t)r1 * ldc + c + 1] = acc[i][j][3] + b1;
                }
            }
        }
    }
}

struct GemmArgs {
    const float* A; int lda;
    const float* W; int ldw;
    const float* bias;
    float* C; int ldc;
};

__global__ __launch_bounds__(256)
void gemm_tc_dual(GemmArgs a0, GemmArgs a1, int M, int N, int K)
{
    const GemmArgs& g = blockIdx.z ? a1 : a0;
    gemm_tc_body(g.A, g.lda, g.W, g.ldw, g.bias, g.C, g.ldc, M, N, K);
}

// ---------------- attention (both streams via blockIdx.y) --------------------
struct AttnArgs {
    const int* neigh; const int* nlen; const int* hlen;
    const float* proj; const float* bias; const float* v;
    float* seq; int scol;
};

__global__ void attn_dual(AttnArgs a0, AttnArgs a1,
                          const int* __restrict__ trip,
                          const float* __restrict__ ent,
                          const float* __restrict__ rel)
{
    const AttnArgs& a = blockIdx.y ? a1 : a0;
    const int bt = blockIdx.x;
    const int b = bt / Tt, t = bt % Tt;
    __shared__ float s_bias[Hh], s_v[Hh];
    __shared__ float s_logit[Nn], s_w[Nn];
    __shared__ int s_nidx[Nn];
    const int tid = threadIdx.x;
    for (int g = tid; g < Hh; g += 256) { s_bias[g] = a.bias[b * Hh + g]; s_v[g] = a.v[g]; }
    for (int n = tid; n < Nn; n += 256) s_nidx[n] = a.neigh[((size_t)b * Tt + t) * Nn + n];
    __syncthreads();
    const int nl = a.nlen[b * Tt + t];
    const int warp = tid >> 5, lane = tid & 31;
    for (int n = warp; n < nl; n += 8) {
        const float* pr = a.proj + (size_t)s_nidx[n] * Hh;
        float acc = 0.f;
        for (int g = lane; g < Hh; g += 32)
            acc += tanh_fast(pr[g] + s_bias[g]) * s_v[g];
        for (int o = 16; o; o >>= 1) acc += __shfl_xor_sync(0xffffffffu, acc, o);
        if (lane == 0) s_logit[n] = acc;
    }
    __syncthreads();
    if (warp == 0) {
        float m = -3.4e38f;
        for (int n = lane; n < nl; n += 32) m = fmaxf(m, s_logit[n]);
        for (int o = 16; o; o >>= 1) m = fmaxf(m, __shfl_xor_sync(0xffffffffu, m, o));
        float s = 0.f;
        for (int n = lane; n < nl; n += 32) { float e = expf(s_logit[n] - m); s_w[n] = e; s += e; }
        for (int o = 16; o; o >>= 1) s += __shfl_xor_sync(0xffffffffu, s, o);
        float inv = 1.f / s;
        for (int n = lane; n < nl; n += 32) s_w[n] *= inv;
    }
    __syncthreads();
    const float msk = (t < a.hlen[b]) ? 1.f : 0.f;
    const int sid = trip[b * 3 + a.scol], rid = trip[b * 3 + 1];
    float* out = a.seq + ((size_t)b * Tt + t) * H3;
    for (int h = tid; h < Hh; h += 256) {
        float acc = 0.f;
        for (int n = 0; n < nl; n++) acc += s_w[n] * ent[(size_t)s_nidx[n] * Hh + h];
        out[h]          = round_tf32(acc * msk);
        out[Hh + h]     = round_tf32(ent[(size_t)sid * Hh + h] * msk);
        out[2 * Hh + h] = round_tf32(rel[(size_t)rid * Hh + h] * msk);
    }
}

// ---------------- fused GRU: whole T-loop in one launch -----------------------
__global__ __launch_bounds__(256)
void gru_fused(const float* __restrict__ Whh_s, const float* __restrict__ bhh_s,
               const float* __restrict__ Whh_o, const float* __restrict__ bhh_o,
               const int* __restrict__ slen, const int* __restrict__ olen)
{
    const int z = blockIdx.y;
    const float* Whh = z ? Whh_o : Whh_s;
    const float* bhh = z ? bhh_o : bhh_s;
    const float* gi  = z ? g_gi_o : g_gi_s;
    float* hout      = z ? g_h_o : g_h_s;
    const int* len   = z ? olen : slen;
    const int b0 = blockIdx.x * 8;
    const int tid = threadIdx.x;

    __shared__ float h_sm[8][Hh];
    __shared__ float gh_sm[8][H3];
    __shared__ int   len_sm[8];

    for (int i = tid; i < 8 * Hh; i += 256) h_sm[i / Hh][i % Hh] = 0.f;
    if (tid < 8) len_sm[tid] = len[b0 + tid];
    __syncthreads();

    for (int t = 0; t < Tt; t++) {
        for (int j = tid; j < H3; j += 256) {
            const float* wrow = Whh + (size_t)j * Hh;
            float acc[8];
#pragma unroll
            for (int b = 0; b < 8; b++) acc[b] = 0.f;
            for (int k = 0; k < Hh; k += 4) {
                float4 w = *(const float4*)(wrow + k);
#pragma unroll
                for (int b = 0; b < 8; b++) {
                    float4 h4 = *(const float4*)&h_sm[b][k];
                    acc[b] += w.x * h4.x + w.y * h4.y + w.z * h4.z + w.w * h4.w;
                }
            }
            float bb = bhh[j];
#pragma unroll
            for (int b = 0; b < 8; b++) gh_sm[b][j] = acc[b] + bb;
        }
        __syncthreads();

        for (int idx = tid; idx < 8 * Hh; idx += 256) {
            int b = idx / Hh, jj = idx % Hh;
            if (t < len_sm[b]) {
                const float* gib = gi + ((size_t)(b0 + b) * Tt + t) * H3;
                float ir = gib[jj], iz = gib[Hh + jj], in = gib[2 * Hh + jj];
                float hr = gh_sm[b][jj], hz = gh_sm[b][Hh + jj], hn = gh_sm[b][2 * Hh + jj];
                float rg = 1.f / (1.f + expf(-(ir + hr)));
                float zg = 1.f / (1.f + expf(-(iz + hz)));
                float ng = tanhf(in + rg * hn);
                h_sm[b][jj] = (1.f - zg) * ng + zg * h_sm[b][jj];
            }
        }
        __syncthreads();
    }

    for (int i = tid; i < 8 * Hh; i += 256)
        hout[(size_t)(b0 + i / Hh) * Hh + (i % Hh)] = h_sm[i / Hh][i % Hh];
}

// ---------------- final feature assembly (both streams) ----------------------
__global__ void feat_dual(const int* __restrict__ trip,
                          const float* __restrict__ ent, const float* __restrict__ rel)
{
    int b = blockIdx.x, z = blockIdx.y;
    const int* idx = z ? g_oidx : g_sidx;
    const float* h = z ? g_h_o : g_h_s;
    float* feat    = z ? g_feat_o : g_feat_s;
    int scol = z ? 2 : 0;
    int p = idx[b];
    int sid = trip[p * 3 + scol], rid = trip[p * 3 + 1];
    for (int i = threadIdx.x; i < Hh; i += 256) {
        feat[(size_t)b * H3 + i]        = round_tf32(ent[(size_t)sid * Hh + i]);
        feat[(size_t)b * H3 + Hh + i]   = round_tf32(h[(size_t)p * Hh + i]);
        feat[(size_t)b * H3 + 2*Hh + i] = round_tf32(rel[(size_t)rid * Hh + i]);
    }
}

// ---------------- cross-entropy: single-pass online softmax (both streams) ---
__global__ void ce_dual(const float* __restrict__ predA,   // ob_pred (out+1+BE)
                        const float* __restrict__ predB,   // sub_pred (out+1)
                        const int* __restrict__ trip)
{
    int b = blockIdx.x, z = blockIdx.y;
    const float* row = (z ? predB : predA) + (size_t)b * Ee;
    const int* idx = z ? g_oidx : g_sidx;
    int labcol = z ? 0 : 2;
    float* lp = z ? g_lp1 : g_lp0;
    int tid = threadIdx.x;
    int lane = tid & 31, warp = tid >> 5;
    __shared__ float smax[8], ssum[8];

    float m = -3.4e38f, s = 0.f;
    for (int i = tid; i < Ee; i += 256) {
        float v = row[i];
        float nm = fmaxf(m, v);
        s = s * expf(m - nm) + expf(v - nm);
        m = nm;
    }
    for (int o = 16; o; o >>= 1) {
        float mo = __shfl_xor_sync(0xffffffffu, m, o);
        float so = __shfl_xor_sync(0xffffffffu, s, o);
        float nm = fmaxf(m, mo);
        s = s * expf(m - nm) + so * expf(mo - nm);
        m = nm;
    }
    if (lane == 0) { smax[warp] = m; ssum[warp] = s; }
    __syncthreads();
    if (tid == 0) {
        float mm = smax[0], st = ssum[0];
        for (int i = 1; i < 8; i++) {
            float nm = fmaxf(mm, smax[i]);
            st = st * expf(mm - nm) + ssum[i] * expf(smax[i] - nm);
            mm = nm;
        }
        int lab = trip[idx[b] * 3 + labcol];
        lp[b] = row[lab] - mm - logf(st);
    }
}

// ---------------- finalize: loss + index outputs ------------------------------
__global__ void finalize_kernel(float* __restrict__ out)
{
    int tid = threadIdx.x;
    if (tid == 0) {
        double a = 0.0, c = 0.0;
        for (int b = 0; b < Bq; b++) { a += (double)g_lp0[b]; c += (double)g_lp1[b]; }
        out[0] = (float)(-(a / (double)Bq) - (c / (double)Bq));
    }
    for (int b = tid; b < Bq; b += blockDim.x) {
        out[1 + 2 * (size_t)BE + b]       = (float)g_oidx[b];
        out[1 + 2 * (size_t)BE + Bq + b]  = (float)g_sidx[b];
    }
}

// ---------------- host-side orchestration ------------------------------------
extern "C" void kernel_launch(void* const* d_in, const int* in_sizes, int n_in,
                              void* d_out, int out_size)
{
    const int*   trip     = (const int*)d_in[0];
    const int*   s_neigh  = (const int*)d_in[1];
    const int*   s_nlen   = (const int*)d_in[2];
    const int*   s_hlen   = (const int*)d_in[3];
    const int*   o_neigh  = (const int*)d_in[4];
    const int*   o_nlen   = (const int*)d_in[5];
    const int*   o_hlen   = (const int*)d_in[6];
    const float* ent      = (const float*)d_in[7];
    const float* rel      = (const float*)d_in[8];
    const float* attn_s_w = (const float*)d_in[9];
    const float* attn_s_b = (const float*)d_in[10];
    const float* v_s      = (const float*)d_in[11];
    const float* attn_o_w = (const float*)d_in[12];
    const float* attn_o_b = (const float*)d_in[13];
    const float* v_o      = (const float*)d_in[14];
    const float* sub_w_ih = (const float*)d_in[15];
    const float* sub_w_hh = (const float*)d_in[16];
    const float* sub_b_ih = (const float*)d_in[17];
    const float* sub_b_hh = (const float*)d_in[18];
    const float* ob_w_ih  = (const float*)d_in[19];
    const float* ob_w_hh  = (const float*)d_in[20];
    const float* ob_b_ih  = (const float*)d_in[21];
    const float* ob_b_hh  = (const float*)d_in[22];
    const float* lin_sub_w = (const float*)d_in[23];
    const float* lin_sub_b = (const float*)d_in[24];
    const float* lin_ob_w  = (const float*)d_in[25];
    const float* lin_ob_b  = (const float*)d_in[26];
    float* out = (float*)d_out;

    float *proj_s, *proj_o, *x_s, *x_o, *bias_s, *bias_o, *seq_s, *seq_o;
    float *gi_s, *gi_o;
    float *ent_r, *wa_s, *wa_o, *wih_s, *wih_o, *wlin_s, *wlin_o;
    float *feat_s, *feat_o;
    cudaGetSymbolAddress((void**)&proj_s, g_proj_s);
    cudaGetSymbolAddress((void**)&proj_o, g_proj_o);
    cudaGetSymbolAddress((void**)&x_s,    g_x_s);
    cudaGetSymbolAddress((void**)&x_o,    g_x_o);
    cudaGetSymbolAddress((void**)&bias_s, g_bias_s);
    cudaGetSymbolAddress((void**)&bias_o, g_bias_o);
    cudaGetSymbolAddress((void**)&seq_s,  g_seq_s);
    cudaGetSymbolAddress((void**)&seq_o,  g_seq_o);
    cudaGetSymbolAddress((void**)&gi_s,   g_gi_s);
    cudaGetSymbolAddress((void**)&gi_o,   g_gi_o);
    cudaGetSymbolAddress((void**)&feat_s, g_feat_s);
    cudaGetSymbolAddress((void**)&feat_o, g_feat_o);
    cudaGetSymbolAddress((void**)&ent_r,  g_ent_r);
    cudaGetSymbolAddress((void**)&wa_s,   g_wa_s);
    cudaGetSymbolAddress((void**)&wa_o,   g_wa_o);
    cudaGetSymbolAddress((void**)&wih_s,  g_wih_s);
    cudaGetSymbolAddress((void**)&wih_o,  g_wih_o);
    cudaGetSymbolAddress((void**)&wlin_s, g_wlin_s);
    cudaGetSymbolAddress((void**)&wlin_o, g_wlin_o);

    // 0) pre-round all static GEMM inputs to tf32
    round_all<<<dim3(256, 7), 256>>>(ent, attn_s_w, attn_o_w,
                                     sub_w_ih, ob_w_ih, lin_sub_w, lin_ob_w);

    // 1) sort + X gather (rounded)
    sort_kernel<<<1, 1024>>>(s_hlen, o_hlen);
    gather_x<<<dim3(Bq, 2), 128>>>(trip, ent);

    // 2) entity projections (dual)  M=Ee,N=Hh,K=Hh
    {
        GemmArgs a0{ent_r, Hh, wa_s, H3, nullptr, proj_s, Hh};
        GemmArgs a1{ent_r, Hh, wa_o, H3, nullptr, proj_o, Hh};
        dim3 g((Hh + 63) / 64, (Ee + 127) / 128, 2);
        gemm_tc_dual<<<g, 256>>>(a0, a1, Ee, Hh, Hh);
    }

    // 3) bias GEMM (dual)  M=Bq,N=Hh,K=2H
    {
        GemmArgs a0{x_s, H2, wa_s + Hh, H3, attn_s_b, bias_s, Hh};
        GemmArgs a1{x_o, H2, wa_o + Hh, H3, attn_o_b, bias_o, Hh};
        dim3 g((Hh + 63) / 64, (Bq + 127) / 128, 2);
        gemm_tc_dual<<<g, 256>>>(a0, a1, Bq, Hh, H2);
    }

    // 4) attention (both streams, one launch)
    {
        AttnArgs a0{s_neigh, s_nlen, s_hlen, proj_s, bias_s, v_s, seq_s, 0};
        AttnArgs a1{o_neigh, o_nlen, o_hlen, proj_o, bias_o, v_o, seq_o, 2};
        attn_dual<<<dim3(Bq * Tt, 2), 256>>>(a0, a1, trip, ent, rel);
    }

    // 5) GRU input gates (dual)  M=B*T,N=3H,K=3H
    {
        GemmArgs a0{seq_s, H3, wih_s, H3, sub_b_ih, gi_s, H3};
        GemmArgs a1{seq_o, H3, wih_o, H3, ob_b_ih,  gi_o, H3};
        dim3 g((H3 + 63) / 64, (Bq * Tt + 127) / 128, 2);
        gemm_tc_dual<<<g, 256>>>(a0, a1, Bq * Tt, H3, H3);
    }

    // 6) fused GRU — whole T-loop, both streams, one launch
    gru_fused<<<dim3(Bq / 8, 2), 256>>>(sub_w_hh, sub_b_hh, ob_w_hh, ob_b_hh,
                                        s_hlen, o_hlen);

    // 7) permuted feature assembly (both streams, one launch)
    feat_dual<<<dim3(Bq, 2), 256>>>(trip, ent, rel);

    // 8) prediction GEMMs into d_out (dual)  M=Bq,N=Ee,K=3H
    //    layout: [loss(1) | sub_pred(B*E) | ob_pred(B*E) | o_idx(B) | s_idx(B)]
    {
        GemmArgs a0{feat_s, H3, wlin_s, H3, lin_sub_b, out + 1 + (size_t)BE, Ee};
        GemmArgs a1{feat_o, H3, wlin_o, H3, lin_ob_b,  out + 1,              Ee};
        dim3 g((Ee + 63) / 64, (Bq + 127) / 128, 2);
        gemm_tc_dual<<<g, 256>>>(a0, a1, Bq, Ee, H3);
    }

    // 9) CE log-probs (both streams, one launch) + finalize
    ce_dual<<<dim3(Bq, 2), 256>>>(out + 1 + (size_t)BE, out + 1, trip);
    finalize_kernel<<<1, 512>>>(out);
}

// round 17
// speedup vs baseline: 1.1478x; 1.0187x over previous
#include <cuda_runtime.h>
#include <cuda_fp16.h>
#include <math.h>
#include <stdint.h>

// Problem constants
#define Bq 512
#define Tt 10
#define Nn 50
#define Hh 200
#define Ee 10000
#define Rr 200
#define H3 600
#define H2 400
#define BE (Bq*Ee)

// ---------------- scratch (static __device__, no allocations) ----------------
__device__ float g_proj_s[Ee*Hh];
__device__ float g_proj_o[Ee*Hh];
__device__ float g_bias_s[Bq*Hh];
__device__ float g_bias_o[Bq*Hh];
__device__ float g_gi_s[Bq*Tt*H3];
__device__ float g_gi_o[Bq*Tt*H3];
__device__ float g_h_s[Bq*Hh];
__device__ float g_h_o[Bq*Hh];
__device__ float g_lp0[Bq];
__device__ float g_lp1[Bq];
__device__ int   g_sidx[Bq];
__device__ int   g_oidx[Bq];

// fp16 GEMM inputs (converted ONCE for statics; produced directly for dynamics)
__device__ __half g_ent_h [Ee*Hh];
__device__ __half g_wa_s  [Hh*H3];
__device__ __half g_wa_o  [Hh*H3];
__device__ __half g_wih_s [H3*H3];
__device__ __half g_wih_o [H3*H3];
__device__ __half g_wlin_s[Ee*H3];
__device__ __half g_wlin_o[Ee*H3];
__device__ __half g_x_s   [Bq*H2];
__device__ __half g_x_o   [Bq*H2];
__device__ __half g_seq_s [Bq*Tt*H3];
__device__ __half g_seq_o [Bq*Tt*H3];
__device__ __half g_feat_s[Bq*H3];
__device__ __half g_feat_o[Bq*H3];

__device__ __forceinline__ float tanh_fast(float x) {
    float y;
    asm("tanh.approx.f32 %0, %1;" : "=f"(y) : "f"(x));
    return y;
}

__device__ __forceinline__ void mma_f16(float* d, const uint32_t* a, uint32_t b) {
    asm volatile(
        "mma.sync.aligned.m16n8k8.row.col.f32.f16.f16.f32 "
        "{%0,%1,%2,%3}, {%4,%5}, {%6}, {%0,%1,%2,%3};"
        : "+f"(d[0]), "+f"(d[1]), "+f"(d[2]), "+f"(d[3])
        : "r"(a[0]), "r"(a[1]), "r"(b));
}

__device__ __forceinline__ void cp16(uint32_t dst, const __half* src) {
    asm volatile("cp.async.cg.shared.global [%0], [%1], 16;" :: "r"(dst), "l"(src));
}
__device__ __forceinline__ void cp_commit() {
    asm volatile("cp.async.commit_group;");
}

// ---------------- convert all static GEMM inputs to fp16 ---------------------
__global__ void half_all(const float* __restrict__ ent,
                         const float* __restrict__ wa_s, const float* __restrict__ wa_o,
                         const float* __restrict__ wih_s, const float* __restrict__ wih_o,
                         const float* __restrict__ wlin_s, const float* __restrict__ wlin_o)
{
    const float* src; __half* dst; int n4;
    switch (blockIdx.y) {
        case 0: src = ent;    dst = g_ent_h;  n4 = Ee*Hh/4;  break;
        case 1: src = wa_s;   dst = g_wa_s;   n4 = Hh*H3/4;  break;
        case 2: src = wa_o;   dst = g_wa_o;   n4 = Hh*H3/4;  break;
        case 3: src = wih_s;  dst = g_wih_s;  n4 = H3*H3/4;  break;
        case 4: src = wih_o;  dst = g_wih_o;  n4 = H3*H3/4;  break;
        case 5: src = wlin_s; dst = g_wlin_s; n4 = Ee*H3/4;  break;
        default: src = wlin_o; dst = g_wlin_o; n4 = Ee*H3/4; break;
    }
    int stride = gridDim.x * blockDim.x;
    for (int i = blockIdx.x * blockDim.x + threadIdx.x; i < n4; i += stride) {
        float4 v = ((const float4*)src)[i];
        __half2 lo = __floats2half2_rn(v.x, v.y);
        __half2 hi = __floats2half2_rn(v.z, v.w);
        ((__half2*)dst)[2*i]   = lo;
        ((__half2*)dst)[2*i+1] = hi;
    }
}

// ---------------- parallel stable descending argsort (rank-based) ------------
__global__ void sort_kernel(const int* __restrict__ s_hlen, const int* __restrict__ o_hlen)
{
    __shared__ int sv[Bq], ov[Bq];
    int t = threadIdx.x;
    int b = t & 511;
    if (t < 512) sv[b] = s_hlen[b]; else ov[b] = o_hlen[b];
    __syncthreads();
    const int* L = (t < 512) ? sv : ov;
    int lv = L[b];
    int r = 0;
    for (int j = 0; j < Bq; j++) {
        int v = L[j];
        r += (v > lv) || (v == lv && j < b);
    }
    if (t < 512) g_sidx[r] = b; else g_oidx[r] = b;
}

// ---------------- gather X = [ent[sid] || ent[rid]] (fp16) -------------------
__global__ void gather_x(const int* __restrict__ trip, const float* __restrict__ ent)
{
    int b = blockIdx.x, z = blockIdx.y;
    __half* X = (z ? g_x_o : g_x_s) + (size_t)b * H2;
    int scol = z ? 2 : 0;
    int sid = trip[b * 3 + scol], rid = trip[b * 3 + 1];
    for (int i = threadIdx.x; i < Hh; i += 128) {
        X[i]      = __float2half_rn(ent[(size_t)sid * Hh + i]);
        X[Hh + i] = __float2half_rn(ent[(size_t)rid * Hh + i]);
    }
}

// ============ fp16 tensor-core GEMM: C[M,N] = A[M,K] @ W[N,K]^T (+bias) ======
// 256 threads / 8 warps; CTA tile 128x64; warp tile 32x32 = 2x4 m16n8k8.f16.
// Pair-pipelined 6-stage smem ring (per k-tile: A 2KB, W 1KB; conflict-free
// fragment LDS, bank = 4*gid+tig bijective). fp32 accumulate, scalar C stores.
// A/W must be fp16 with 16B-aligned rows; K % 8 == 0.
__device__ __forceinline__
void gemm_tc_body(const __half* __restrict__ A, int lda,
                  const __half* __restrict__ W, int ldw,
                  const float* __restrict__ bias,
                  float* __restrict__ C, int ldc,
                  int M, int N, int K)
{
    __shared__ __half As[6][128][8];
    __shared__ __half Ws[6][64][8];

    const int tid  = threadIdx.x;
    const int bm   = blockIdx.y * 128;
    const int bn   = blockIdx.x * 64;
    const int wid  = tid >> 5, lane = tid & 31;
    const int gid  = lane >> 2, tig = lane & 3;
    const int wm   = (wid & 3) * 32;
    const int wn   = (wid >> 2) * 32;

    // staging: threads 0..127 stage A rows (16B each); 128..191 stage W rows.
    const bool isA = tid < 128;
    const bool isW = (tid >= 128) && (tid < 192);
    uint32_t dSm = 0;
    const __half* gSrc = A;
    if (isA) {
        int rA = bm + tid; if (rA > M - 1) rA = M - 1;
        gSrc = A + (size_t)rA * lda;
        dSm = (uint32_t)__cvta_generic_to_shared(&As[0][tid][0]);
    } else if (isW) {
        int rn = tid - 128;
        int rW = bn + rn; if (rW > N - 1) rW = N - 1;
        gSrc = W + (size_t)rW * ldw;
        dSm = (uint32_t)__cvta_generic_to_shared(&Ws[0][rn][0]);
    }
    const uint32_t A_ST = 128 * 16;            // bytes per A stage
    const uint32_t W_ST = 64 * 16;
    const uint32_t ST = isA ? A_ST : W_ST;
    const bool doCp = isA || isW;

    const int nt = K >> 3;
    const int np = (nt + 1) >> 1;

    // prologue: pair 0 -> stages {0,1}; pair 1 -> stages {2,3}
    {
        if (doCp) cp16(dSm, gSrc);
        if (1 < nt && doCp) cp16(dSm + ST, gSrc + 8);
        cp_commit();
        if (2 < nt && doCp) {
            cp16(dSm + 2 * ST, gSrc + 16);
            if (3 < nt) cp16(dSm + 3 * ST, gSrc + 24);
        }
        cp_commit();
    }

    float acc[2][4][4];
#pragma unroll
    for (int i = 0; i < 2; i++)
#pragma unroll
        for (int j = 0; j < 4; j++)
#pragma unroll
            for (int e = 0; e < 4; e++) acc[i][j][e] = 0.f;

    for (int p = 0; p < np; p++) {
        if (p < np - 1) asm volatile("cp.async.wait_group 1;");
        else            asm volatile("cp.async.wait_group 0;");
        __syncthreads();

        // prefetch pair p+2 into pair-slot (p+2)%3 (consumed at iter p-1, safe)
        {
            int q = p + 2;
            if (q < np && doCp) {
                int st = (q - (q / 3) * 3) * 2;     // (q%3)*2
                int kt0 = q * 2;
                cp16(dSm + (uint32_t)st * ST, gSrc + kt0 * 8);
                if (kt0 + 1 < nt)
                    cp16(dSm + (uint32_t)(st + 1) * ST, gSrc + (kt0 + 1) * 8);
            }
            cp_commit();
        }

        // consume the two sub-tiles of pair p
        const int base = (p - (p / 3) * 3) * 2;     // (p%3)*2
#pragma unroll
        for (int sub = 0; sub < 2; sub++) {
            int kt = 2 * p + sub;
            if (kt >= nt) break;
            const int buf = base + sub;
            uint32_t afr[2][2], bfr[4];
#pragma unroll
            for (int i = 0; i < 2; i++) {
                int mb = wm + 16 * i + gid;
                afr[i][0] = *(const uint32_t*)&As[buf][mb    ][2 * tig];
                afr[i][1] = *(const uint32_t*)&As[buf][mb + 8][2 * tig];
            }
#pragma unroll
            for (int j = 0; j < 4; j++) {
                int nb = wn + 8 * j + gid;
                bfr[j] = *(const uint32_t*)&Ws[buf][nb][2 * tig];
            }
#pragma unroll
            for (int i = 0; i < 2; i++)
#pragma unroll
                for (int j = 0; j < 4; j++)
                    mma_f16(acc[i][j], afr[i], bfr[j]);
        }
    }

    // epilogue (scalar stores — C may be misaligned, e.g. d_out+1)
#pragma unroll
    for (int i = 0; i < 2; i++) {
        int r0 = bm + wm + 16 * i + gid;
        int r1 = r0 + 8;
#pragma unroll
        for (int j = 0; j < 4; j++) {
            int c = bn + wn + 8 * j + 2 * tig;
            if (c < N) {
                float b0 = bias ? bias[c]     : 0.f;
                float b1 = bias ? bias[c + 1] : 0.f;
                if (r0 < M) {
                    C[(size_t)r0 * ldc + c]     = acc[i][j][0] + b0;
                    C[(size_t)r0 * ldc + c + 1] = acc[i][j][1] + b1;
                }
                if (r1 < M) {
                    C[(size_t)r1 * ldc + c]     = acc[i][j][2] + b0;
                    C[(size_t)r1 * ldc + c + 1] = acc[i][j][3] + b1;
                }
            }
        }
    }
}

struct GemmArgs {
    const __half* A; int lda;
    const __half* W; int ldw;
    const float* bias;
    float* C; int ldc;
};

__global__ __launch_bounds__(256)
void gemm_tc_dual(GemmArgs a0, GemmArgs a1, int M, int N, int K)
{
    const GemmArgs& g = blockIdx.z ? a1 : a0;
    gemm_tc_body(g.A, g.lda, g.W, g.ldw, g.bias, g.C, g.ldc, M, N, K);
}

// ---------------- attention (both streams via blockIdx.y) --------------------
struct AttnArgs {
    const int* neigh; const int* nlen; const int* hlen;
    const float* proj; const float* bias; const float* v;
    __half* seq; int scol;
};

__global__ void attn_dual(AttnArgs a0, AttnArgs a1,
                          const int* __restrict__ trip,
                          const float* __restrict__ ent,
                          const float* __restrict__ rel)
{
    const AttnArgs& a = blockIdx.y ? a1 : a0;
    const int bt = blockIdx.x;
    const int b = bt / Tt, t = bt % Tt;
    __shared__ float s_bias[Hh], s_v[Hh];
    __shared__ float s_logit[Nn], s_w[Nn];
    __shared__ int s_nidx[Nn];
    const int tid = threadIdx.x;
    for (int g = tid; g < Hh; g += 256) { s_bias[g] = a.bias[b * Hh + g]; s_v[g] = a.v[g]; }
    for (int n = tid; n < Nn; n += 256) s_nidx[n] = a.neigh[((size_t)b * Tt + t) * Nn + n];
    __syncthreads();
    const int nl = a.nlen[b * Tt + t];
    const int warp = tid >> 5, lane = tid & 31;
    for (int n = warp; n < nl; n += 8) {
        const float* pr = a.proj + (size_t)s_nidx[n] * Hh;
        float acc = 0.f;
        for (int g = lane; g < Hh; g += 32)
            acc += tanh_fast(pr[g] + s_bias[g]) * s_v[g];
        for (int o = 16; o; o >>= 1) acc += __shfl_xor_sync(0xffffffffu, acc, o);
        if (lane == 0) s_logit[n] = acc;
    }
    __syncthreads();
    if (warp == 0) {
        float m = -3.4e38f;
        for (int n = lane; n < nl; n += 32) m = fmaxf(m, s_logit[n]);
        for (int o = 16; o; o >>= 1) m = fmaxf(m, __shfl_xor_sync(0xffffffffu, m, o));
        float s = 0.f;
        for (int n = lane; n < nl; n += 32) { float e = expf(s_logit[n] - m); s_w[n] = e; s += e; }
        for (int o = 16; o; o >>= 1) s += __shfl_xor_sync(0xffffffffu, s, o);
        float inv = 1.f / s;
        for (int n = lane; n < nl; n += 32) s_w[n] *= inv;
    }
    __syncthreads();
    const float msk = (t < a.hlen[b]) ? 1.f : 0.f;
    const int sid = trip[b * 3 + a.scol], rid = trip[b * 3 + 1];
    __half* out = a.seq + ((size_t)b * Tt + t) * H3;
    for (int h = tid; h < Hh; h += 256) {
        float acc = 0.f;
        for (int n = 0; n < nl; n++) acc += s_w[n] * ent[(size_t)s_nidx[n] * Hh + h];
        out[h]          = __float2half_rn(acc * msk);
        out[Hh + h]     = __float2half_rn(ent[(size_t)sid * Hh + h] * msk);
        out[2 * Hh + h] = __float2half_rn(rel[(size_t)rid * Hh + h] * msk);
    }
}

// ---------------- fused GRU: whole T-loop in one launch -----------------------
__global__ __launch_bounds__(256)
void gru_fused(const float* __restrict__ Whh_s, const float* __restrict__ bhh_s,
               const float* __restrict__ Whh_o, const float* __restrict__ bhh_o,
               const int* __restrict__ slen, const int* __restrict__ olen)
{
    const int z = blockIdx.y;
    const float* Whh = z ? Whh_o : Whh_s;
    const float* bhh = z ? bhh_o : bhh_s;
    const float* gi  = z ? g_gi_o : g_gi_s;
    float* hout      = z ? g_h_o : g_h_s;
    const int* len   = z ? olen : slen;
    const int b0 = blockIdx.x * 8;
    const int tid = threadIdx.x;

    __shared__ float h_sm[8][Hh];
    __shared__ float gh_sm[8][H3];
    __shared__ int   len_sm[8];

    for (int i = tid; i < 8 * Hh; i += 256) h_sm[i / Hh][i % Hh] = 0.f;
    if (tid < 8) len_sm[tid] = len[b0 + tid];
    __syncthreads();

    for (int t = 0; t < Tt; t++) {
        for (int j = tid; j < H3; j += 256) {
            const float* wrow = Whh + (size_t)j * Hh;
            float acc[8];
#pragma unroll
            for (int b = 0; b < 8; b++) acc[b] = 0.f;
            for (int k = 0; k < Hh; k += 4) {
                float4 w = *(const float4*)(wrow + k);
#pragma unroll
                for (int b = 0; b < 8; b++) {
                    float4 h4 = *(const float4*)&h_sm[b][k];
                    acc[b] += w.x * h4.x + w.y * h4.y + w.z * h4.z + w.w * h4.w;
                }
            }
            float bb = bhh[j];
#pragma unroll
            for (int b = 0; b < 8; b++) gh_sm[b][j] = acc[b] + bb;
        }
        __syncthreads();

        for (int idx = tid; idx < 8 * Hh; idx += 256) {
            int b = idx / Hh, jj = idx % Hh;
            if (t < len_sm[b]) {
                const float* gib = gi + ((size_t)(b0 + b) * Tt + t) * H3;
                float ir = gib[jj], iz = gib[Hh + jj], in = gib[2 * Hh + jj];
                float hr = gh_sm[b][jj], hz = gh_sm[b][Hh + jj], hn = gh_sm[b][2 * Hh + jj];
                float rg = 1.f / (1.f + expf(-(ir + hr)));
                float zg = 1.f / (1.f + expf(-(iz + hz)));
                float ng = tanhf(in + rg * hn);
                h_sm[b][jj] = (1.f - zg) * ng + zg * h_sm[b][jj];
            }
        }
        __syncthreads();
    }

    for (int i = tid; i < 8 * Hh; i += 256)
        hout[(size_t)(b0 + i / Hh) * Hh + (i % Hh)] = h_sm[i / Hh][i % Hh];
}

// ---------------- final feature assembly (fp16; both streams) ----------------
__global__ void feat_dual(const int* __restrict__ trip,
                          const float* __restrict__ ent, const float* __restrict__ rel)
{
    int b = blockIdx.x, z = blockIdx.y;
    const int* idx = z ? g_oidx : g_sidx;
    const float* h = z ? g_h_o : g_h_s;
    __half* feat   = z ? g_feat_o : g_feat_s;
    int scol = z ? 2 : 0;
    int p = idx[b];
    int sid = trip[p * 3 + scol], rid = trip[p * 3 + 1];
    for (int i = threadIdx.x; i < Hh; i += 256) {
        feat[(size_t)b * H3 + i]        = __float2half_rn(ent[(size_t)sid * Hh + i]);
        feat[(size_t)b * H3 + Hh + i]   = __float2half_rn(h[(size_t)p * Hh + i]);
        feat[(size_t)b * H3 + 2*Hh + i] = __float2half_rn(rel[(size_t)rid * Hh + i]);
    }
}

// ---------------- cross-entropy: single-pass online softmax (both streams) ---
__global__ void ce_dual(const float* __restrict__ predA,   // ob_pred (out+1+BE)
                        const float* __restrict__ predB,   // sub_pred (out+1)
                        const int* __restrict__ trip)
{
    int b = blockIdx.x, z = blockIdx.y;
    const float* row = (z ? predB : predA) + (size_t)b * Ee;
    const int* idx = z ? g_oidx : g_sidx;
    int labcol = z ? 0 : 2;
    float* lp = z ? g_lp1 : g_lp0;
    int tid = threadIdx.x;
    int lane = tid & 31, warp = tid >> 5;
    __shared__ float smax[8], ssum[8];

    float m = -3.4e38f, s = 0.f;
    for (int i = tid; i < Ee; i += 256) {
        float v = row[i];
        float nm = fmaxf(m, v);
        s = s * expf(m - nm) + expf(v - nm);
        m = nm;
    }
    for (int o = 16; o; o >>= 1) {
        float mo = __shfl_xor_sync(0xffffffffu, m, o);
        float so = __shfl_xor_sync(0xffffffffu, s, o);
        float nm = fmaxf(m, mo);
        s = s * expf(m - nm) + so * expf(mo - nm);
        m = nm;
    }
    if (lane == 0) { smax[warp] = m; ssum[warp] = s; }
    __syncthreads();
    if (tid == 0) {
        float mm = smax[0], st = ssum[0];
        for (int i = 1; i < 8; i++) {
            float nm = fmaxf(mm, smax[i]);
            st = st * expf(mm - nm) + ssum[i] * expf(smax[i] - nm);
            mm = nm;
        }
        int lab = trip[idx[b] * 3 + labcol];
        lp[b] = row[lab] - mm - logf(st);
    }
}

// ---------------- finalize: loss + index outputs ------------------------------
__global__ void finalize_kernel(float* __restrict__ out)
{
    int tid = threadIdx.x;
    if (tid == 0) {
        double a = 0.0, c = 0.0;
        for (int b = 0; b < Bq; b++) { a += (double)g_lp0[b]; c += (double)g_lp1[b]; }
        out[0] = (float)(-(a / (double)Bq) - (c / (double)Bq));
    }
    for (int b = tid; b < Bq; b += blockDim.x) {
        out[1 + 2 * (size_t)BE + b]       = (float)g_oidx[b];
        out[1 + 2 * (size_t)BE + Bq + b]  = (float)g_sidx[b];
    }
}

// ---------------- host-side orchestration ------------------------------------
extern "C" void kernel_launch(void* const* d_in, const int* in_sizes, int n_in,
                              void* d_out, int out_size)
{
    const int*   trip     = (const int*)d_in[0];
    const int*   s_neigh  = (const int*)d_in[1];
    const int*   s_nlen   = (const int*)d_in[2];
    const int*   s_hlen   = (const int*)d_in[3];
    const int*   o_neigh  = (const int*)d_in[4];
    const int*   o_nlen   = (const int*)d_in[5];
    const int*   o_hlen   = (const int*)d_in[6];
    const float* ent      = (const float*)d_in[7];
    const float* rel      = (const float*)d_in[8];
    const float* attn_s_w = (const float*)d_in[9];
    const float* attn_s_b = (const float*)d_in[10];
    const float* v_s      = (const float*)d_in[11];
    const float* attn_o_w = (const float*)d_in[12];
    const float* attn_o_b = (const float*)d_in[13];
    const float* v_o      = (const float*)d_in[14];
    const float* sub_w_ih = (const float*)d_in[15];
    const float* sub_w_hh = (const float*)d_in[16];
    const float* sub_b_ih = (const float*)d_in[17];
    const float* sub_b_hh = (const float*)d_in[18];
    const float* ob_w_ih  = (const float*)d_in[19];
    const float* ob_w_hh  = (const float*)d_in[20];
    const float* ob_b_ih  = (const float*)d_in[21];
    const float* ob_b_hh  = (const float*)d_in[22];
    const float* lin_sub_w = (const float*)d_in[23];
    const float* lin_sub_b = (const float*)d_in[24];
    const float* lin_ob_w  = (const float*)d_in[25];
    const float* lin_ob_b  = (const float*)d_in[26];
    float* out = (float*)d_out;

    float *proj_s, *proj_o, *bias_s, *bias_o, *gi_s, *gi_o;
    __half *ent_h, *wa_s, *wa_o, *wih_s, *wih_o, *wlin_s, *wlin_o;
    __half *x_s, *x_o, *seq_s, *seq_o, *feat_s, *feat_o;
    cudaGetSymbolAddress((void**)&proj_s, g_proj_s);
    cudaGetSymbolAddress((void**)&proj_o, g_proj_o);
    cudaGetSymbolAddress((void**)&bias_s, g_bias_s);
    cudaGetSymbolAddress((void**)&bias_o, g_bias_o);
    cudaGetSymbolAddress((void**)&gi_s,   g_gi_s);
    cudaGetSymbolAddress((void**)&gi_o,   g_gi_o);
    cudaGetSymbolAddress((void**)&ent_h,  g_ent_h);
    cudaGetSymbolAddress((void**)&wa_s,   g_wa_s);
    cudaGetSymbolAddress((void**)&wa_o,   g_wa_o);
    cudaGetSymbolAddress((void**)&wih_s,  g_wih_s);
    cudaGetSymbolAddress((void**)&wih_o,  g_wih_o);
    cudaGetSymbolAddress((void**)&wlin_s, g_wlin_s);
    cudaGetSymbolAddress((void**)&wlin_o, g_wlin_o);
    cudaGetSymbolAddress((void**)&x_s,    g_x_s);
    cudaGetSymbolAddress((void**)&x_o,    g_x_o);
    cudaGetSymbolAddress((void**)&seq_s,  g_seq_s);
    cudaGetSymbolAddress((void**)&seq_o,  g_seq_o);
    cudaGetSymbolAddress((void**)&feat_s, g_feat_s);
    cudaGetSymbolAddress((void**)&feat_o, g_feat_o);

    // 0) convert all static GEMM inputs to fp16
    half_all<<<dim3(256, 7), 256>>>(ent, attn_s_w, attn_o_w,
                                    sub_w_ih, ob_w_ih, lin_sub_w, lin_ob_w);

    // 1) sort + X gather (fp16)
    sort_kernel<<<1, 1024>>>(s_hlen, o_hlen);
    gather_x<<<dim3(Bq, 2), 128>>>(trip, ent);

    // 2) entity projections (dual)  M=Ee,N=Hh,K=Hh
    {
        GemmArgs a0{ent_h, Hh, wa_s, H3, nullptr, proj_s, Hh};
        GemmArgs a1{ent_h, Hh, wa_o, H3, nullptr, proj_o, Hh};
        dim3 g((Hh + 63) / 64, (Ee + 127) / 128, 2);
        gemm_tc_dual<<<g, 256>>>(a0, a1, Ee, Hh, Hh);
    }

    // 3) bias GEMM (dual)  M=Bq,N=Hh,K=2H
    {
        GemmArgs a0{x_s, H2, wa_s + Hh, H3, attn_s_b, bias_s, Hh};
        GemmArgs a1{x_o, H2, wa_o + Hh, H3, attn_o_b, bias_o, Hh};
        dim3 g((Hh + 63) / 64, (Bq + 127) / 128, 2);
        gemm_tc_dual<<<g, 256>>>(a0, a1, Bq, Hh, H2);
    }

    // 4) attention (both streams, one launch) -> fp16 seq
    {
        AttnArgs a0{s_neigh, s_nlen, s_hlen, proj_s, bias_s, v_s, seq_s, 0};
        AttnArgs a1{o_neigh, o_nlen, o_hlen, proj_o, bias_o, v_o, seq_o, 2};
        attn_dual<<<dim3(Bq * Tt, 2), 256>>>(a0, a1, trip, ent, rel);
    }

    // 5) GRU input gates (dual)  M=B*T,N=3H,K=3H
    {
        GemmArgs a0{seq_s, H3, wih_s, H3, sub_b_ih, gi_s, H3};
        GemmArgs a1{seq_o, H3, wih_o, H3, ob_b_ih,  gi_o, H3};
        dim3 g((H3 + 63) / 64, (Bq * Tt + 127) / 128, 2);
        gemm_tc_dual<<<g, 256>>>(a0, a1, Bq * Tt, H3, H3);
    }

    // 6) fused GRU — whole T-loop, both streams, one launch
    gru_fused<<<dim3(Bq / 8, 2), 256>>>(sub_w_hh, sub_b_hh, ob_w_hh, ob_b_hh,
                                        s_hlen, o_hlen);

    // 7) permuted feature assembly (fp16; both streams, one launch)
    feat_dual<<<dim3(Bq, 2), 256>>>(trip, ent, rel);

    // 8) prediction GEMMs into d_out (dual)  M=Bq,N=Ee,K=3H
    //    layout: [loss(1) | sub_pred(B*E) | ob_pred(B*E) | o_idx(B) | s_idx(B)]
    {
        GemmArgs a0{feat_s, H3, wlin_s, H3, lin_sub_b, out + 1 + (size_t)BE, Ee};
        GemmArgs a1{feat_o, H3, wlin_o, H3, lin_ob_b,  out + 1,              Ee};
        dim3 g((Ee + 63) / 64, (Bq + 127) / 128, 2);
        gemm_tc_dual<<<g, 256>>>(a0, a1, Bq, Ee, H3);
    }

    // 9) CE log-probs (both streams, one launch) + finalize
    ce_dual<<<dim3(Bq, 2), 256>>>(out + 1 + (size_t)BE, out + 1, trip);
    finalize_kernel<<<1, 512>>>(out);
}